// round 3
// baseline (speedup 1.0000x reference)
#include <cuda_runtime.h>
#include <cstdint>
#include <math.h>

#define NT 512
#define NH 2048
#define NE 60
#define NI 1408
#define NS 5632
#define KTOP 4
#define NPAIR (NT*KTOP)

// ---------------- device scratch (static, no allocations) ----------------
__device__ __align__(16) float g_Abuf[NPAIR * NI];   // routed act:  [2048, 1408]
__device__ __align__(16) float g_Bsh[NT * NS];       // shared act:  [512, 5632]
__device__ int   g_pair_tok[NPAIR];
__device__ float g_pair_w[NPAIR];
__device__ int   g_cnt[NE];
__device__ int   g_off[NE + 1];
__device__ int   g_cur[NE];
__device__ float g_sg[NT];
__device__ int   g_tok_e[NT * KTOP];
__device__ float g_tok_w[NT * KTOP];

// ---------------- helpers ----------------
__device__ __forceinline__ uint32_t f2tf(float x) {
    uint32_t r; asm("cvt.rna.tf32.f32 %0, %1;" : "=r"(r) : "f"(x)); return r;
}
__device__ __forceinline__ void mma8(float* c, const uint32_t* a, const uint32_t* b) {
    asm volatile(
        "mma.sync.aligned.m16n8k8.row.col.f32.tf32.tf32.f32 "
        "{%0,%1,%2,%3}, {%4,%5,%6,%7}, {%8,%9}, {%0,%1,%2,%3};"
        : "+f"(c[0]), "+f"(c[1]), "+f"(c[2]), "+f"(c[3])
        : "r"(a[0]), "r"(a[1]), "r"(a[2]), "r"(a[3]), "r"(b[0]), "r"(b[1]));
}
__device__ __forceinline__ void cpa16(void* s, const void* g) {
    uint32_t sa = (uint32_t)__cvta_generic_to_shared(s);
    asm volatile("cp.async.cg.shared.global [%0], [%1], 16;" :: "r"(sa), "l"(g));
}
__device__ __forceinline__ void cpcommit() { asm volatile("cp.async.commit_group;"); }
__device__ __forceinline__ void cpwait1()  { asm volatile("cp.async.wait_group 1;"); }
__device__ __forceinline__ void cpwait0()  { asm volatile("cp.async.wait_group 0;"); }

__device__ __forceinline__ float silu_mul(float h1, float h3) {
    return h3 * (h1 / (1.0f + expf(-h1)));
}

// ---------------- init: zero routing counters ----------------
__global__ void k_init() {
    int i = threadIdx.x;
    if (i < NE) { g_cnt[i] = 0; g_cur[i] = 0; }
}

// ---------------- router: logits, softmax, top-4, sigmoid shared gate ----------------
__global__ __launch_bounds__(256) void k_router(const float* __restrict__ x,
                                                const float* __restrict__ gw,
                                                const float* __restrict__ sgw) {
    __shared__ __align__(16) float xs[4][NH];
    __shared__ float lg[4][64];
    const int t0 = blockIdx.x * 4;
    const int tid = threadIdx.x;

    const float4* xg = reinterpret_cast<const float4*>(x + (size_t)t0 * NH);
    float4* xv = reinterpret_cast<float4*>(&xs[0][0]);
    for (int i = tid; i < 4 * NH / 4; i += 256) xv[i] = xg[i];
    __syncthreads();

    if (tid < 4 * 61) {
        const int tl = tid / 61, e = tid % 61;
        float acc = 0.f;
        if (e < NE) {
            #pragma unroll 8
            for (int h = 0; h < NH; h++) acc += xs[tl][h] * gw[h * NE + e];
            lg[tl][e] = acc;
        } else {
            #pragma unroll 8
            for (int h = 0; h < NH; h++) acc += xs[tl][h] * sgw[h];
            g_sg[t0 + tl] = 1.f / (1.f + expf(-acc));
        }
    }
    __syncthreads();

    if (tid < 4) {
        float mx = -1e30f;
        for (int e = 0; e < NE; e++) mx = fmaxf(mx, lg[tid][e]);
        float s = 0.f;
        for (int e = 0; e < NE; e++) { float p = expf(lg[tid][e] - mx); lg[tid][e] = p; s += p; }
        const float inv = 1.f / s;
        for (int k = 0; k < KTOP; k++) {
            float best = -1.f; int bi = 0;
            for (int e = 0; e < NE; e++) { float v = lg[tid][e]; if (v > best) { best = v; bi = e; } }
            lg[tid][bi] = -2.f;
            g_tok_e[(t0 + tid) * KTOP + k] = bi;
            g_tok_w[(t0 + tid) * KTOP + k] = best * inv;
            atomicAdd(&g_cnt[bi], 1);
        }
    }
}

__global__ void k_scan() {
    if (threadIdx.x == 0) {
        int o = 0;
        for (int e = 0; e < NE; e++) { g_off[e] = o; o += g_cnt[e]; }
        g_off[NE] = o;
    }
}

__global__ void k_scatter() {
    const int t = blockIdx.x * 256 + threadIdx.x;
    if (t < NT) {
        for (int k = 0; k < KTOP; k++) {
            const int e = g_tok_e[t * KTOP + k];
            const int p = g_off[e] + atomicAdd(&g_cur[e], 1);
            g_pair_tok[p] = t;
            g_pair_w[p] = g_tok_w[t * KTOP + k];
        }
    }
}

// ---------------- shared up: g_Bsh = silu(X@W1s) * (X@W3s) ----------------
// block tile 128x64, BK=16, dual weights, 8 warps (4x2) -> warp tile 32x32
__global__ __launch_bounds__(256) void k_shared_up(const float* __restrict__ x,
                                                   const float* __restrict__ w1,
                                                   const float* __restrict__ w3) {
    __shared__ __align__(16) float As[2][128][20];
    __shared__ __align__(16) float B1s[2][16][72];
    __shared__ __align__(16) float B3s[2][16][72];

    const int tid = threadIdx.x;
    const int m0 = blockIdx.y * 128;
    const int n0 = blockIdx.x * 64;
    const int lane = tid & 31, warp = tid >> 5;
    const int g = lane >> 2, tg = lane & 3;
    const int wm = (warp >> 1) * 32, wn = (warp & 1) * 32;
    const int ar = tid >> 2, ac = (tid & 3) * 4;
    const int br = tid >> 4, bc = (tid & 15) * 4;

    float c1[2][4][4], c3[2][4][4];
    #pragma unroll
    for (int i = 0; i < 2; i++)
        #pragma unroll
        for (int j = 0; j < 4; j++)
            #pragma unroll
            for (int l = 0; l < 4; l++) { c1[i][j][l] = 0.f; c3[i][j][l] = 0.f; }

    auto load_stage = [&](int st, int kk) {
        const int k0 = kk * 16;
        cpa16(&As[st][ar][ac],      x  + (size_t)(m0 + ar) * NH + k0 + ac);
        cpa16(&As[st][ar + 64][ac], x  + (size_t)(m0 + ar + 64) * NH + k0 + ac);
        cpa16(&B1s[st][br][bc],     w1 + (size_t)(k0 + br) * NS + n0 + bc);
        cpa16(&B3s[st][br][bc],     w3 + (size_t)(k0 + br) * NS + n0 + bc);
    };
    load_stage(0, 0); cpcommit();

    const int NKI = NH / 16;
    for (int kk = 0; kk < NKI; ++kk) {
        const int st = kk & 1;
        if (kk + 1 < NKI) { load_stage(st ^ 1, kk + 1); cpcommit(); cpwait1(); }
        else cpwait0();
        __syncthreads();
        #pragma unroll
        for (int k8 = 0; k8 < 2; k8++) {
            const int kb = k8 * 8;
            uint32_t a[2][4];
            #pragma unroll
            for (int im = 0; im < 2; im++) {
                const int r = wm + im * 16;
                a[im][0] = f2tf(As[st][r + g    ][kb + tg    ]);
                a[im][1] = f2tf(As[st][r + g + 8][kb + tg    ]);
                a[im][2] = f2tf(As[st][r + g    ][kb + tg + 4]);
                a[im][3] = f2tf(As[st][r + g + 8][kb + tg + 4]);
            }
            #pragma unroll
            for (int in = 0; in < 4; in++) {
                const int cn = wn + in * 8 + g;
                uint32_t b1v[2], b3v[2];
                b1v[0] = f2tf(B1s[st][kb + tg    ][cn]);
                b1v[1] = f2tf(B1s[st][kb + tg + 4][cn]);
                b3v[0] = f2tf(B3s[st][kb + tg    ][cn]);
                b3v[1] = f2tf(B3s[st][kb + tg + 4][cn]);
                #pragma unroll
                for (int im = 0; im < 2; im++) {
                    mma8(c1[im][in], a[im], b1v);
                    mma8(c3[im][in], a[im], b3v);
                }
            }
        }
        __syncthreads();
    }

    #pragma unroll
    for (int im = 0; im < 2; im++) {
        const int row = m0 + wm + im * 16 + g;
        #pragma unroll
        for (int in = 0; in < 4; in++) {
            const int col = n0 + wn + in * 8 + tg * 2;
            float v0 = silu_mul(c1[im][in][0], c3[im][in][0]);
            float v1 = silu_mul(c1[im][in][1], c3[im][in][1]);
            float v2 = silu_mul(c1[im][in][2], c3[im][in][2]);
            float v3 = silu_mul(c1[im][in][3], c3[im][in][3]);
            *reinterpret_cast<float2*>(&g_Bsh[(size_t)row * NS + col])       = make_float2(v0, v1);
            *reinterpret_cast<float2*>(&g_Bsh[(size_t)(row + 8) * NS + col]) = make_float2(v2, v3);
        }
    }
}

// ---------------- shared down: out = sg[t] * (g_Bsh @ W2s) ----------------
__global__ __launch_bounds__(256) void k_shared_down(float* __restrict__ out,
                                                     const float* __restrict__ w2) {
    __shared__ __align__(16) float As[2][128][20];
    __shared__ __align__(16) float Bs[2][16][72];

    const int tid = threadIdx.x;
    const int m0 = blockIdx.y * 128;
    const int n0 = blockIdx.x * 64;
    const int lane = tid & 31, warp = tid >> 5;
    const int g = lane >> 2, tg = lane & 3;
    const int wm = (warp >> 1) * 32, wn = (warp & 1) * 32;
    const int ar = tid >> 2, ac = (tid & 3) * 4;
    const int br = tid >> 4, bc = (tid & 15) * 4;

    float c[2][4][4];
    #pragma unroll
    for (int i = 0; i < 2; i++)
        #pragma unroll
        for (int j = 0; j < 4; j++)
            #pragma unroll
            for (int l = 0; l < 4; l++) c[i][j][l] = 0.f;

    auto load_stage = [&](int st, int kk) {
        const int k0 = kk * 16;
        cpa16(&As[st][ar][ac],      g_Bsh + (size_t)(m0 + ar) * NS + k0 + ac);
        cpa16(&As[st][ar + 64][ac], g_Bsh + (size_t)(m0 + ar + 64) * NS + k0 + ac);
        cpa16(&Bs[st][br][bc],      w2 + (size_t)(k0 + br) * NH + n0 + bc);
    };
    load_stage(0, 0); cpcommit();

    const int NKI = NS / 16;
    for (int kk = 0; kk < NKI; ++kk) {
        const int st = kk & 1;
        if (kk + 1 < NKI) { load_stage(st ^ 1, kk + 1); cpcommit(); cpwait1(); }
        else cpwait0();
        __syncthreads();
        #pragma unroll
        for (int k8 = 0; k8 < 2; k8++) {
            const int kb = k8 * 8;
            uint32_t a[2][4];
            #pragma unroll
            for (int im = 0; im < 2; im++) {
                const int r = wm + im * 16;
                a[im][0] = f2tf(As[st][r + g    ][kb + tg    ]);
                a[im][1] = f2tf(As[st][r + g + 8][kb + tg    ]);
                a[im][2] = f2tf(As[st][r + g    ][kb + tg + 4]);
                a[im][3] = f2tf(As[st][r + g + 8][kb + tg + 4]);
            }
            #pragma unroll
            for (int in = 0; in < 4; in++) {
                const int cn = wn + in * 8 + g;
                uint32_t bv[2];
                bv[0] = f2tf(Bs[st][kb + tg    ][cn]);
                bv[1] = f2tf(Bs[st][kb + tg + 4][cn]);
                #pragma unroll
                for (int im = 0; im < 2; im++) mma8(c[im][in], a[im], bv);
            }
        }
        __syncthreads();
    }

    #pragma unroll
    for (int im = 0; im < 2; im++) {
        const int row = m0 + wm + im * 16 + g;
        const float s0 = g_sg[row], s1 = g_sg[row + 8];
        #pragma unroll
        for (int in = 0; in < 4; in++) {
            const int col = n0 + wn + in * 8 + tg * 2;
            *reinterpret_cast<float2*>(&out[(size_t)row * NH + col])       = make_float2(s0 * c[im][in][0], s0 * c[im][in][1]);
            *reinterpret_cast<float2*>(&out[(size_t)(row + 8) * NH + col]) = make_float2(s1 * c[im][in][2], s1 * c[im][in][3]);
        }
    }
}

// ---------------- routed up: g_Abuf[pair] = silu(Xe@w1e) * (Xe@w3e) ----------------
// block tile 64x64, dual weights, 8 warps (4x2) -> warp tile 16x32
__global__ __launch_bounds__(256) void k_moe_up(const float* __restrict__ x,
                                                const float* __restrict__ w1,
                                                const float* __restrict__ w3) {
    const int e = blockIdx.y;
    const int seg0 = g_off[e];
    const int ne = g_off[e + 1] - seg0;
    const int m0 = blockIdx.z * 64;
    if (m0 >= ne) return;
    const int n0 = blockIdx.x * 64;

    __shared__ __align__(16) float As[2][64][20];
    __shared__ __align__(16) float B1s[2][16][72];
    __shared__ __align__(16) float B3s[2][16][72];

    const int tid = threadIdx.x;
    const int lane = tid & 31, warp = tid >> 5;
    const int g = lane >> 2, tg = lane & 3;
    const int wm = (warp >> 1) * 16, wn = (warp & 1) * 32;
    const int ar = tid >> 2, ac = (tid & 3) * 4;
    const int br = tid >> 4, bc = (tid & 15) * 4;

    const int prow = m0 + ar;
    const float* arow = x + (size_t)g_pair_tok[seg0 + (prow < ne ? prow : 0)] * NH;
    const float* w1e = w1 + (size_t)e * NH * NI;
    const float* w3e = w3 + (size_t)e * NH * NI;

    float c1[4][4], c3[4][4];
    #pragma unroll
    for (int j = 0; j < 4; j++)
        #pragma unroll
        for (int l = 0; l < 4; l++) { c1[j][l] = 0.f; c3[j][l] = 0.f; }

    auto load_stage = [&](int st, int kk) {
        const int k0 = kk * 16;
        cpa16(&As[st][ar][ac], arow + k0 + ac);
        cpa16(&B1s[st][br][bc], w1e + (size_t)(k0 + br) * NI + n0 + bc);
        cpa16(&B3s[st][br][bc], w3e + (size_t)(k0 + br) * NI + n0 + bc);
    };
    load_stage(0, 0); cpcommit();

    const int NKI = NH / 16;
    for (int kk = 0; kk < NKI; ++kk) {
        const int st = kk & 1;
        if (kk + 1 < NKI) { load_stage(st ^ 1, kk + 1); cpcommit(); cpwait1(); }
        else cpwait0();
        __syncthreads();
        #pragma unroll
        for (int k8 = 0; k8 < 2; k8++) {
            const int kb = k8 * 8;
            uint32_t a[4];
            a[0] = f2tf(As[st][wm + g    ][kb + tg    ]);
            a[1] = f2tf(As[st][wm + g + 8][kb + tg    ]);
            a[2] = f2tf(As[st][wm + g    ][kb + tg + 4]);
            a[3] = f2tf(As[st][wm + g + 8][kb + tg + 4]);
            #pragma unroll
            for (int in = 0; in < 4; in++) {
                const int cn = wn + in * 8 + g;
                uint32_t b1v[2], b3v[2];
                b1v[0] = f2tf(B1s[st][kb + tg    ][cn]);
                b1v[1] = f2tf(B1s[st][kb + tg + 4][cn]);
                b3v[0] = f2tf(B3s[st][kb + tg    ][cn]);
                b3v[1] = f2tf(B3s[st][kb + tg + 4][cn]);
                mma8(c1[in], a, b1v);
                mma8(c3[in], a, b3v);
            }
        }
        __syncthreads();
    }

    const int lr = wm + g;
    const bool vr0 = (m0 + lr) < ne;
    const bool vr1 = (m0 + lr + 8) < ne;
    float* o0 = &g_Abuf[(size_t)(seg0 + m0 + lr) * NI];
    float* o1 = o0 + (size_t)8 * NI;
    #pragma unroll
    for (int in = 0; in < 4; in++) {
        const int col = n0 + wn + in * 8 + tg * 2;
        if (vr0) *reinterpret_cast<float2*>(o0 + col) =
            make_float2(silu_mul(c1[in][0], c3[in][0]), silu_mul(c1[in][1], c3[in][1]));
        if (vr1) *reinterpret_cast<float2*>(o1 + col) =
            make_float2(silu_mul(c1[in][2], c3[in][2]), silu_mul(c1[in][3], c3[in][3]));
    }
}

// ---------------- routed down: out[tok] += pair_w * (Abuf_seg @ w2e) ----------------
__global__ __launch_bounds__(256) void k_moe_down(float* __restrict__ out,
                                                  const float* __restrict__ w2) {
    const int e = blockIdx.y;
    const int seg0 = g_off[e];
    const int ne = g_off[e + 1] - seg0;
    const int m0 = blockIdx.z * 64;
    if (m0 >= ne) return;
    const int n0 = blockIdx.x * 64;

    __shared__ __align__(16) float As[2][64][20];
    __shared__ __align__(16) float Bs[2][16][72];

    const int tid = threadIdx.x;
    const int lane = tid & 31, warp = tid >> 5;
    const int g = lane >> 2, tg = lane & 3;
    const int wm = (warp >> 1) * 16, wn = (warp & 1) * 32;
    const int ar = tid >> 2, ac = (tid & 3) * 4;
    const int br = tid >> 4, bc = (tid & 15) * 4;

    int aidx = seg0 + m0 + ar;
    if (aidx > NPAIR - 1) aidx = NPAIR - 1;
    const float* arow = g_Abuf + (size_t)aidx * NI;
    const float* w2e = w2 + (size_t)e * NI * NH;

    float c[4][4];
    #pragma unroll
    for (int j = 0; j < 4; j++)
        #pragma unroll
        for (int l = 0; l < 4; l++) c[j][l] = 0.f;

    auto load_stage = [&](int st, int kk) {
        const int k0 = kk * 16;
        cpa16(&As[st][ar][ac], arow + k0 + ac);
        cpa16(&Bs[st][br][bc], w2e + (size_t)(k0 + br) * NH + n0 + bc);
    };
    load_stage(0, 0); cpcommit();

    const int NKI = NI / 16;
    for (int kk = 0; kk < NKI; ++kk) {
        const int st = kk & 1;
        if (kk + 1 < NKI) { load_stage(st ^ 1, kk + 1); cpcommit(); cpwait1(); }
        else cpwait0();
        __syncthreads();
        #pragma unroll
        for (int k8 = 0; k8 < 2; k8++) {
            const int kb = k8 * 8;
            uint32_t a[4];
            a[0] = f2tf(As[st][wm + g    ][kb + tg    ]);
            a[1] = f2tf(As[st][wm + g + 8][kb + tg    ]);
            a[2] = f2tf(As[st][wm + g    ][kb + tg + 4]);
            a[3] = f2tf(As[st][wm + g + 8][kb + tg + 4]);
            #pragma unroll
            for (int in = 0; in < 4; in++) {
                const int cn = wn + in * 8 + g;
                uint32_t bv[2];
                bv[0] = f2tf(Bs[st][kb + tg    ][cn]);
                bv[1] = f2tf(Bs[st][kb + tg + 4][cn]);
                mma8(c[in], a, bv);
            }
        }
        __syncthreads();
    }

    const int lr = wm + g;
    if (m0 + lr < ne) {
        const int p = seg0 + m0 + lr;
        const int t = g_pair_tok[p];
        const float w = g_pair_w[p];
        float* orow = out + (size_t)t * NH;
        #pragma unroll
        for (int in = 0; in < 4; in++) {
            const int col = n0 + wn + in * 8 + tg * 2;
            atomicAdd(orow + col,     w * c[in][0]);
            atomicAdd(orow + col + 1, w * c[in][1]);
        }
    }
    if (m0 + lr + 8 < ne) {
        const int p = seg0 + m0 + lr + 8;
        const int t = g_pair_tok[p];
        const float w = g_pair_w[p];
        float* orow = out + (size_t)t * NH;
        #pragma unroll
        for (int in = 0; in < 4; in++) {
            const int col = n0 + wn + in * 8 + tg * 2;
            atomicAdd(orow + col,     w * c[in][2]);
            atomicAdd(orow + col + 1, w * c[in][3]);
        }
    }
}

// ---------------- launch ----------------
extern "C" void kernel_launch(void* const* d_in, const int* in_sizes, int n_in,
                              void* d_out, int out_size) {
    const float* x   = (const float*)d_in[0];
    const float* gw  = (const float*)d_in[1];
    const float* w1  = (const float*)d_in[2];
    const float* w3  = (const float*)d_in[3];
    const float* w2  = (const float*)d_in[4];
    const float* sw1 = (const float*)d_in[5];
    const float* sw3 = (const float*)d_in[6];
    const float* sw2 = (const float*)d_in[7];
    const float* sgw = (const float*)d_in[8];
    float* out = (float*)d_out;

    k_init<<<1, 64>>>();
    k_router<<<NT / 4, 256>>>(x, gw, sgw);
    k_scan<<<1, 32>>>();
    k_scatter<<<2, 256>>>();

    // shared expert: up (fused gate/up + silu), then down (+sigmoid gate) writes out
    k_shared_up<<<dim3(NS / 64, NT / 128), 256>>>(x, sw1, sw3);
    // routed experts: up (fused, gathered rows)
    k_moe_up<<<dim3(NI / 64, NE, 8), 256>>>(x, w1, w3);
    // shared down writes every out element (out is poisoned before timing)
    k_shared_down<<<dim3(NH / 64, NT / 128), 256>>>(out, sw2);
    // routed down accumulates into out via atomics
    k_moe_down<<<dim3(NH / 64, NE, 8), 256>>>(out, w2);
}

// round 4
// speedup vs baseline: 1.1395x; 1.1395x over previous
#include <cuda_runtime.h>
#include <cstdint>
#include <math.h>

#define NT 512
#define NH 2048
#define NE 60
#define NI 1408
#define NS 5632
#define KTOP 4
#define NPAIR (NT*KTOP)
#define STAGES 4

// ---------------- device scratch (static, no allocations) ----------------
__device__ __align__(16) float g_Abuf[NPAIR * NI];   // routed act:  [2048, 1408]
__device__ __align__(16) float g_Bsh[NT * NS];       // shared act:  [512, 5632]
__device__ int   g_pair_tok[NPAIR];
__device__ float g_pair_w[NPAIR];
__device__ int   g_cnt[NE];
__device__ int   g_off[NE + 1];
__device__ int   g_cur[NE];
__device__ float g_sg[NT];
__device__ int   g_tok_e[NT * KTOP];
__device__ float g_tok_w[NT * KTOP];

// ---------------- helpers ----------------
__device__ __forceinline__ uint32_t f2tf(float x) {
    uint32_t r; asm("cvt.rna.tf32.f32 %0, %1;" : "=r"(r) : "f"(x)); return r;
}
__device__ __forceinline__ void mma8(float* c, const uint32_t* a, const uint32_t* b) {
    asm volatile(
        "mma.sync.aligned.m16n8k8.row.col.f32.tf32.tf32.f32 "
        "{%0,%1,%2,%3}, {%4,%5,%6,%7}, {%8,%9}, {%0,%1,%2,%3};"
        : "+f"(c[0]), "+f"(c[1]), "+f"(c[2]), "+f"(c[3])
        : "r"(a[0]), "r"(a[1]), "r"(a[2]), "r"(a[3]), "r"(b[0]), "r"(b[1]));
}
__device__ __forceinline__ void cpa16(void* s, const void* g) {
    uint32_t sa = (uint32_t)__cvta_generic_to_shared(s);
    asm volatile("cp.async.cg.shared.global [%0], [%1], 16;" :: "r"(sa), "l"(g));
}
__device__ __forceinline__ void cpcommit() { asm volatile("cp.async.commit_group;"); }
__device__ __forceinline__ void cpwaitS2() { asm volatile("cp.async.wait_group %0;" :: "n"(STAGES - 2)); }

__device__ __forceinline__ float silu_mul(float h1, float h3) {
    return h3 * (h1 / (1.0f + expf(-h1)));
}

// ---------------- init: zero routing counters ----------------
__global__ void k_init() {
    int i = threadIdx.x;
    if (i < NE) { g_cnt[i] = 0; g_cur[i] = 0; }
}

// ---------------- router: logits, softmax, top-4, sigmoid shared gate ----------------
__global__ __launch_bounds__(256) void k_router(const float* __restrict__ x,
                                                const float* __restrict__ gw,
                                                const float* __restrict__ sgw) {
    __shared__ __align__(16) float xs[4][NH];
    __shared__ float lg[4][64];
    const int t0 = blockIdx.x * 4;
    const int tid = threadIdx.x;

    const float4* xg = reinterpret_cast<const float4*>(x + (size_t)t0 * NH);
    float4* xv = reinterpret_cast<float4*>(&xs[0][0]);
    for (int i = tid; i < 4 * NH / 4; i += 256) xv[i] = xg[i];
    __syncthreads();

    if (tid < 4 * 61) {
        const int tl = tid / 61, e = tid % 61;
        float acc = 0.f;
        if (e < NE) {
            #pragma unroll 8
            for (int h = 0; h < NH; h++) acc += xs[tl][h] * gw[h * NE + e];
            lg[tl][e] = acc;
        } else {
            #pragma unroll 8
            for (int h = 0; h < NH; h++) acc += xs[tl][h] * sgw[h];
            g_sg[t0 + tl] = 1.f / (1.f + expf(-acc));
        }
    }
    __syncthreads();

    if (tid < 4) {
        float mx = -1e30f;
        for (int e = 0; e < NE; e++) mx = fmaxf(mx, lg[tid][e]);
        float s = 0.f;
        for (int e = 0; e < NE; e++) { float p = expf(lg[tid][e] - mx); lg[tid][e] = p; s += p; }
        const float inv = 1.f / s;
        for (int k = 0; k < KTOP; k++) {
            float best = -1.f; int bi = 0;
            for (int e = 0; e < NE; e++) { float v = lg[tid][e]; if (v > best) { best = v; bi = e; } }
            lg[tid][bi] = -2.f;
            g_tok_e[(t0 + tid) * KTOP + k] = bi;
            g_tok_w[(t0 + tid) * KTOP + k] = best * inv;
            atomicAdd(&g_cnt[bi], 1);
        }
    }
}

__global__ void k_scan() {
    if (threadIdx.x == 0) {
        int o = 0;
        for (int e = 0; e < NE; e++) { g_off[e] = o; o += g_cnt[e]; }
        g_off[NE] = o;
    }
}

__global__ void k_scatter() {
    const int t = blockIdx.x * 256 + threadIdx.x;
    if (t < NT) {
        for (int k = 0; k < KTOP; k++) {
            const int e = g_tok_e[t * KTOP + k];
            const int p = g_off[e] + atomicAdd(&g_cur[e], 1);
            g_pair_tok[p] = t;
            g_pair_w[p] = g_tok_w[t * KTOP + k];
        }
    }
}

// ---------------- shared up: g_Bsh = silu(X@W1s) * (X@W3s) ----------------
// block tile 128x64, BK=16, dual weights, 8 warps (4x2) -> warp tile 32x32
__global__ __launch_bounds__(256) void k_shared_up(const float* __restrict__ x,
                                                   const float* __restrict__ w1,
                                                   const float* __restrict__ w3) {
    __shared__ __align__(16) float As[STAGES][128][20];
    __shared__ __align__(16) float B1s[STAGES][16][72];
    __shared__ __align__(16) float B3s[STAGES][16][72];

    const int tid = threadIdx.x;
    const int m0 = blockIdx.y * 128;
    const int n0 = blockIdx.x * 64;
    const int lane = tid & 31, warp = tid >> 5;
    const int g = lane >> 2, tg = lane & 3;
    const int wm = (warp >> 1) * 32, wn = (warp & 1) * 32;
    const int ar = tid >> 2, ac = (tid & 3) * 4;
    const int br = tid >> 4, bc = (tid & 15) * 4;

    float c1[2][4][4], c3[2][4][4];
    #pragma unroll
    for (int i = 0; i < 2; i++)
        #pragma unroll
        for (int j = 0; j < 4; j++)
            #pragma unroll
            for (int l = 0; l < 4; l++) { c1[i][j][l] = 0.f; c3[i][j][l] = 0.f; }

    auto load_stage = [&](int st, int kk) {
        const int k0 = kk * 16;
        cpa16(&As[st][ar][ac],      x  + (size_t)(m0 + ar) * NH + k0 + ac);
        cpa16(&As[st][ar + 64][ac], x  + (size_t)(m0 + ar + 64) * NH + k0 + ac);
        cpa16(&B1s[st][br][bc],     w1 + (size_t)(k0 + br) * NS + n0 + bc);
        cpa16(&B3s[st][br][bc],     w3 + (size_t)(k0 + br) * NS + n0 + bc);
    };
    #pragma unroll
    for (int s = 0; s < STAGES - 1; s++) { load_stage(s, s); cpcommit(); }

    const int NKI = NH / 16;
    for (int kk = 0; kk < NKI; ++kk) {
        const int st = kk & (STAGES - 1);
        cpwaitS2();
        __syncthreads();
        #pragma unroll
        for (int k8 = 0; k8 < 2; k8++) {
            const int kb = k8 * 8;
            uint32_t a[2][4];
            #pragma unroll
            for (int im = 0; im < 2; im++) {
                const int r = wm + im * 16;
                a[im][0] = f2tf(As[st][r + g    ][kb + tg    ]);
                a[im][1] = f2tf(As[st][r + g + 8][kb + tg    ]);
                a[im][2] = f2tf(As[st][r + g    ][kb + tg + 4]);
                a[im][3] = f2tf(As[st][r + g + 8][kb + tg + 4]);
            }
            #pragma unroll
            for (int in = 0; in < 4; in++) {
                const int cn = wn + in * 8 + g;
                uint32_t b1v[2], b3v[2];
                b1v[0] = f2tf(B1s[st][kb + tg    ][cn]);
                b1v[1] = f2tf(B1s[st][kb + tg + 4][cn]);
                b3v[0] = f2tf(B3s[st][kb + tg    ][cn]);
                b3v[1] = f2tf(B3s[st][kb + tg + 4][cn]);
                #pragma unroll
                for (int im = 0; im < 2; im++) {
                    mma8(c1[im][in], a[im], b1v);
                    mma8(c3[im][in], a[im], b3v);
                }
            }
        }
        if (kk + STAGES - 1 < NKI) load_stage((kk + STAGES - 1) & (STAGES - 1), kk + STAGES - 1);
        cpcommit();
    }

    #pragma unroll
    for (int im = 0; im < 2; im++) {
        const int row = m0 + wm + im * 16 + g;
        #pragma unroll
        for (int in = 0; in < 4; in++) {
            const int col = n0 + wn + in * 8 + tg * 2;
            float v0 = silu_mul(c1[im][in][0], c3[im][in][0]);
            float v1 = silu_mul(c1[im][in][1], c3[im][in][1]);
            float v2 = silu_mul(c1[im][in][2], c3[im][in][2]);
            float v3 = silu_mul(c1[im][in][3], c3[im][in][3]);
            *reinterpret_cast<float2*>(&g_Bsh[(size_t)row * NS + col])       = make_float2(v0, v1);
            *reinterpret_cast<float2*>(&g_Bsh[(size_t)(row + 8) * NS + col]) = make_float2(v2, v3);
        }
    }
}

// ---------------- shared down: out = sg[t] * (g_Bsh @ W2s) ----------------
__global__ __launch_bounds__(256) void k_shared_down(float* __restrict__ out,
                                                     const float* __restrict__ w2) {
    __shared__ __align__(16) float As[STAGES][128][20];
    __shared__ __align__(16) float Bs[STAGES][16][72];

    const int tid = threadIdx.x;
    const int m0 = blockIdx.y * 128;
    const int n0 = blockIdx.x * 64;
    const int lane = tid & 31, warp = tid >> 5;
    const int g = lane >> 2, tg = lane & 3;
    const int wm = (warp >> 1) * 32, wn = (warp & 1) * 32;
    const int ar = tid >> 2, ac = (tid & 3) * 4;
    const int br = tid >> 4, bc = (tid & 15) * 4;

    float c[2][4][4];
    #pragma unroll
    for (int i = 0; i < 2; i++)
        #pragma unroll
        for (int j = 0; j < 4; j++)
            #pragma unroll
            for (int l = 0; l < 4; l++) c[i][j][l] = 0.f;

    auto load_stage = [&](int st, int kk) {
        const int k0 = kk * 16;
        cpa16(&As[st][ar][ac],      g_Bsh + (size_t)(m0 + ar) * NS + k0 + ac);
        cpa16(&As[st][ar + 64][ac], g_Bsh + (size_t)(m0 + ar + 64) * NS + k0 + ac);
        cpa16(&Bs[st][br][bc],      w2 + (size_t)(k0 + br) * NH + n0 + bc);
    };
    #pragma unroll
    for (int s = 0; s < STAGES - 1; s++) { load_stage(s, s); cpcommit(); }

    const int NKI = NS / 16;
    for (int kk = 0; kk < NKI; ++kk) {
        const int st = kk & (STAGES - 1);
        cpwaitS2();
        __syncthreads();
        #pragma unroll
        for (int k8 = 0; k8 < 2; k8++) {
            const int kb = k8 * 8;
            uint32_t a[2][4];
            #pragma unroll
            for (int im = 0; im < 2; im++) {
                const int r = wm + im * 16;
                a[im][0] = f2tf(As[st][r + g    ][kb + tg    ]);
                a[im][1] = f2tf(As[st][r + g + 8][kb + tg    ]);
                a[im][2] = f2tf(As[st][r + g    ][kb + tg + 4]);
                a[im][3] = f2tf(As[st][r + g + 8][kb + tg + 4]);
            }
            #pragma unroll
            for (int in = 0; in < 4; in++) {
                const int cn = wn + in * 8 + g;
                uint32_t bv[2];
                bv[0] = f2tf(Bs[st][kb + tg    ][cn]);
                bv[1] = f2tf(Bs[st][kb + tg + 4][cn]);
                #pragma unroll
                for (int im = 0; im < 2; im++) mma8(c[im][in], a[im], bv);
            }
        }
        if (kk + STAGES - 1 < NKI) load_stage((kk + STAGES - 1) & (STAGES - 1), kk + STAGES - 1);
        cpcommit();
    }

    #pragma unroll
    for (int im = 0; im < 2; im++) {
        const int row = m0 + wm + im * 16 + g;
        const float s0 = g_sg[row], s1 = g_sg[row + 8];
        #pragma unroll
        for (int in = 0; in < 4; in++) {
            const int col = n0 + wn + in * 8 + tg * 2;
            *reinterpret_cast<float2*>(&out[(size_t)row * NH + col])       = make_float2(s0 * c[im][in][0], s0 * c[im][in][1]);
            *reinterpret_cast<float2*>(&out[(size_t)(row + 8) * NH + col]) = make_float2(s1 * c[im][in][2], s1 * c[im][in][3]);
        }
    }
}

// ---------------- routed up: g_Abuf[pair] = silu(Xe@w1e) * (Xe@w3e) ----------------
// block tile 64x64, dual weights, 8 warps (4x2) -> warp tile 16x32
__global__ __launch_bounds__(256) void k_moe_up(const float* __restrict__ x,
                                                const float* __restrict__ w1,
                                                const float* __restrict__ w3) {
    const int e = blockIdx.y;
    const int seg0 = g_off[e];
    const int ne = g_off[e + 1] - seg0;
    const int m0 = blockIdx.z * 64;
    if (m0 >= ne) return;
    const int n0 = blockIdx.x * 64;

    __shared__ __align__(16) float As[STAGES][64][20];
    __shared__ __align__(16) float B1s[STAGES][16][72];
    __shared__ __align__(16) float B3s[STAGES][16][72];

    const int tid = threadIdx.x;
    const int lane = tid & 31, warp = tid >> 5;
    const int g = lane >> 2, tg = lane & 3;
    const int wm = (warp >> 1) * 16, wn = (warp & 1) * 32;
    const int ar = tid >> 2, ac = (tid & 3) * 4;
    const int br = tid >> 4, bc = (tid & 15) * 4;

    const int prow = m0 + ar;
    const float* arow = x + (size_t)g_pair_tok[seg0 + (prow < ne ? prow : 0)] * NH;
    const float* w1e = w1 + (size_t)e * NH * NI;
    const float* w3e = w3 + (size_t)e * NH * NI;

    float c1[4][4], c3[4][4];
    #pragma unroll
    for (int j = 0; j < 4; j++)
        #pragma unroll
        for (int l = 0; l < 4; l++) { c1[j][l] = 0.f; c3[j][l] = 0.f; }

    auto load_stage = [&](int st, int kk) {
        const int k0 = kk * 16;
        cpa16(&As[st][ar][ac], arow + k0 + ac);
        cpa16(&B1s[st][br][bc], w1e + (size_t)(k0 + br) * NI + n0 + bc);
        cpa16(&B3s[st][br][bc], w3e + (size_t)(k0 + br) * NI + n0 + bc);
    };
    #pragma unroll
    for (int s = 0; s < STAGES - 1; s++) { load_stage(s, s); cpcommit(); }

    const int NKI = NH / 16;
    for (int kk = 0; kk < NKI; ++kk) {
        const int st = kk & (STAGES - 1);
        cpwaitS2();
        __syncthreads();
        #pragma unroll
        for (int k8 = 0; k8 < 2; k8++) {
            const int kb = k8 * 8;
            uint32_t a[4];
            a[0] = f2tf(As[st][wm + g    ][kb + tg    ]);
            a[1] = f2tf(As[st][wm + g + 8][kb + tg    ]);
            a[2] = f2tf(As[st][wm + g    ][kb + tg + 4]);
            a[3] = f2tf(As[st][wm + g + 8][kb + tg + 4]);
            #pragma unroll
            for (int in = 0; in < 4; in++) {
                const int cn = wn + in * 8 + g;
                uint32_t b1v[2], b3v[2];
                b1v[0] = f2tf(B1s[st][kb + tg    ][cn]);
                b1v[1] = f2tf(B1s[st][kb + tg + 4][cn]);
                b3v[0] = f2tf(B3s[st][kb + tg    ][cn]);
                b3v[1] = f2tf(B3s[st][kb + tg + 4][cn]);
                mma8(c1[in], a, b1v);
                mma8(c3[in], a, b3v);
            }
        }
        if (kk + STAGES - 1 < NKI) load_stage((kk + STAGES - 1) & (STAGES - 1), kk + STAGES - 1);
        cpcommit();
    }

    const int lr = wm + g;
    const bool vr0 = (m0 + lr) < ne;
    const bool vr1 = (m0 + lr + 8) < ne;
    float* o0 = &g_Abuf[(size_t)(seg0 + m0 + lr) * NI];
    float* o1 = o0 + (size_t)8 * NI;
    #pragma unroll
    for (int in = 0; in < 4; in++) {
        const int col = n0 + wn + in * 8 + tg * 2;
        if (vr0) *reinterpret_cast<float2*>(o0 + col) =
            make_float2(silu_mul(c1[in][0], c3[in][0]), silu_mul(c1[in][1], c3[in][1]));
        if (vr1) *reinterpret_cast<float2*>(o1 + col) =
            make_float2(silu_mul(c1[in][2], c3[in][2]), silu_mul(c1[in][3], c3[in][3]));
    }
}

// ---------------- routed down: out[tok] += pair_w * (Abuf_seg @ w2e) ----------------
__global__ __launch_bounds__(256) void k_moe_down(float* __restrict__ out,
                                                  const float* __restrict__ w2) {
    const int e = blockIdx.y;
    const int seg0 = g_off[e];
    const int ne = g_off[e + 1] - seg0;
    const int m0 = blockIdx.z * 64;
    if (m0 >= ne) return;
    const int n0 = blockIdx.x * 64;

    __shared__ __align__(16) float As[STAGES][64][20];
    __shared__ __align__(16) float Bs[STAGES][16][72];

    const int tid = threadIdx.x;
    const int lane = tid & 31, warp = tid >> 5;
    const int g = lane >> 2, tg = lane & 3;
    const int wm = (warp >> 1) * 16, wn = (warp & 1) * 32;
    const int ar = tid >> 2, ac = (tid & 3) * 4;
    const int br = tid >> 4, bc = (tid & 15) * 4;

    int aidx = seg0 + m0 + ar;
    if (aidx > NPAIR - 1) aidx = NPAIR - 1;
    const float* arow = g_Abuf + (size_t)aidx * NI;
    const float* w2e = w2 + (size_t)e * NI * NH;

    float c[4][4];
    #pragma unroll
    for (int j = 0; j < 4; j++)
        #pragma unroll
        for (int l = 0; l < 4; l++) c[j][l] = 0.f;

    auto load_stage = [&](int st, int kk) {
        const int k0 = kk * 16;
        cpa16(&As[st][ar][ac], arow + k0 + ac);
        cpa16(&Bs[st][br][bc], w2e + (size_t)(k0 + br) * NH + n0 + bc);
    };
    #pragma unroll
    for (int s = 0; s < STAGES - 1; s++) { load_stage(s, s); cpcommit(); }

    const int NKI = NI / 16;
    for (int kk = 0; kk < NKI; ++kk) {
        const int st = kk & (STAGES - 1);
        cpwaitS2();
        __syncthreads();
        #pragma unroll
        for (int k8 = 0; k8 < 2; k8++) {
            const int kb = k8 * 8;
            uint32_t a[4];
            a[0] = f2tf(As[st][wm + g    ][kb + tg    ]);
            a[1] = f2tf(As[st][wm + g + 8][kb + tg    ]);
            a[2] = f2tf(As[st][wm + g    ][kb + tg + 4]);
            a[3] = f2tf(As[st][wm + g + 8][kb + tg + 4]);
            #pragma unroll
            for (int in = 0; in < 4; in++) {
                const int cn = wn + in * 8 + g;
                uint32_t bv[2];
                bv[0] = f2tf(Bs[st][kb + tg    ][cn]);
                bv[1] = f2tf(Bs[st][kb + tg + 4][cn]);
                mma8(c[in], a, bv);
            }
        }
        if (kk + STAGES - 1 < NKI) load_stage((kk + STAGES - 1) & (STAGES - 1), kk + STAGES - 1);
        cpcommit();
    }

    const int lr = wm + g;
    if (m0 + lr < ne) {
        const int p = seg0 + m0 + lr;
        const int t = g_pair_tok[p];
        const float w = g_pair_w[p];
        float* orow = out + (size_t)t * NH;
        #pragma unroll
        for (int in = 0; in < 4; in++) {
            const int col = n0 + wn + in * 8 + tg * 2;
            atomicAdd(orow + col,     w * c[in][0]);
            atomicAdd(orow + col + 1, w * c[in][1]);
        }
    }
    if (m0 + lr + 8 < ne) {
        const int p = seg0 + m0 + lr + 8;
        const int t = g_pair_tok[p];
        const float w = g_pair_w[p];
        float* orow = out + (size_t)t * NH;
        #pragma unroll
        for (int in = 0; in < 4; in++) {
            const int col = n0 + wn + in * 8 + tg * 2;
            atomicAdd(orow + col,     w * c[in][2]);
            atomicAdd(orow + col + 1, w * c[in][3]);
        }
    }
}

// ---------------- launch ----------------
extern "C" void kernel_launch(void* const* d_in, const int* in_sizes, int n_in,
                              void* d_out, int out_size) {
    const float* x   = (const float*)d_in[0];
    const float* gw  = (const float*)d_in[1];
    const float* w1  = (const float*)d_in[2];
    const float* w3  = (const float*)d_in[3];
    const float* w2  = (const float*)d_in[4];
    const float* sw1 = (const float*)d_in[5];
    const float* sw3 = (const float*)d_in[6];
    const float* sw2 = (const float*)d_in[7];
    const float* sgw = (const float*)d_in[8];
    float* out = (float*)d_out;

    k_init<<<1, 64>>>();
    k_router<<<NT / 4, 256>>>(x, gw, sgw);
    k_scan<<<1, 32>>>();
    k_scatter<<<2, 256>>>();

    // shared expert: up (fused gate/up + silu), then down (+sigmoid gate) writes out
    k_shared_up<<<dim3(NS / 64, NT / 128), 256>>>(x, sw1, sw3);
    // routed experts: up (fused, gathered rows)
    k_moe_up<<<dim3(NI / 64, NE, 8), 256>>>(x, w1, w3);
    // shared down writes every out element (out is poisoned before timing)
    k_shared_down<<<dim3(NH / 64, NT / 128), 256>>>(out, sw2);
    // routed down accumulates into out via atomics
    k_moe_down<<<dim3(NH / 64, NE, 8), 256>>>(out, w2);
}

// round 7
// speedup vs baseline: 1.1405x; 1.0009x over previous
#include <cuda_runtime.h>
#include <cstdint>
#include <math.h>

#define NT 512
#define NH 2048
#define NE 60
#define NI 1408
#define NS 5632
#define KTOP 4
#define NPAIR (NT*KTOP)
#define STAGES 4

// ---------------- device scratch (static, no allocations) ----------------
__device__ __align__(16) float g_Abuf[NPAIR * NI];   // routed act:  [2048, 1408]
__device__ __align__(16) float g_Bsh[NT * NS];       // shared act:  [512, 5632]
__device__ int   g_pair_tok[NPAIR];
__device__ float g_pair_w[NPAIR];
__device__ int   g_cnt[NE];
__device__ int   g_off[NE + 1];
__device__ int   g_cur[NE];
__device__ float g_sg[NT];
__device__ int   g_tok_e[NT * KTOP];
__device__ float g_tok_w[NT * KTOP];

// ---------------- helpers ----------------
__device__ __forceinline__ uint32_t f2tf(float x) {
    uint32_t r; asm("cvt.rna.tf32.f32 %0, %1;" : "=r"(r) : "f"(x)); return r;
}
__device__ __forceinline__ void mma8(float* c, const uint32_t* a, const uint32_t* b) {
    asm volatile(
        "mma.sync.aligned.m16n8k8.row.col.f32.tf32.tf32.f32 "
        "{%0,%1,%2,%3}, {%4,%5,%6,%7}, {%8,%9}, {%0,%1,%2,%3};"
        : "+f"(c[0]), "+f"(c[1]), "+f"(c[2]), "+f"(c[3])
        : "r"(a[0]), "r"(a[1]), "r"(a[2]), "r"(a[3]), "r"(b[0]), "r"(b[1]));
}
__device__ __forceinline__ void cpa16(void* s, const void* g) {
    uint32_t sa = (uint32_t)__cvta_generic_to_shared(s);
    asm volatile("cp.async.cg.shared.global [%0], [%1], 16;" :: "r"(sa), "l"(g));
}
__device__ __forceinline__ void cpcommit() { asm volatile("cp.async.commit_group;"); }
__device__ __forceinline__ void cpwaitS2() { asm volatile("cp.async.wait_group %0;" :: "n"(STAGES - 2)); }

__device__ __forceinline__ float silu_mul(float h1, float h3) {
    return h3 * (h1 / (1.0f + expf(-h1)));
}

// ---------------- init: zero routing counters ----------------
__global__ void k_init() {
    int i = threadIdx.x;
    if (i < NE) { g_cnt[i] = 0; g_cur[i] = 0; }
}

// ---------------- router: logits, softmax, top-4, sigmoid shared gate ----------------
__global__ __launch_bounds__(256) void k_router(const float* __restrict__ x,
                                                const float* __restrict__ gw,
                                                const float* __restrict__ sgw) {
    __shared__ __align__(16) float xs[4][NH];
    __shared__ float lg[4][64];
    const int t0 = blockIdx.x * 4;
    const int tid = threadIdx.x;

    const float4* xg = reinterpret_cast<const float4*>(x + (size_t)t0 * NH);
    float4* xv = reinterpret_cast<float4*>(&xs[0][0]);
    for (int i = tid; i < 4 * NH / 4; i += 256) xv[i] = xg[i];
    __syncthreads();

    if (tid < 4 * 61) {
        const int tl = tid / 61, e = tid % 61;
        float acc = 0.f;
        if (e < NE) {
            #pragma unroll 8
            for (int h = 0; h < NH; h++) acc += xs[tl][h] * gw[h * NE + e];
            lg[tl][e] = acc;
        } else {
            #pragma unroll 8
            for (int h = 0; h < NH; h++) acc += xs[tl][h] * sgw[h];
            g_sg[t0 + tl] = 1.f / (1.f + expf(-acc));
        }
    }
    __syncthreads();

    if (tid < 4) {
        float mx = -1e30f;
        for (int e = 0; e < NE; e++) mx = fmaxf(mx, lg[tid][e]);
        float s = 0.f;
        for (int e = 0; e < NE; e++) { float p = expf(lg[tid][e] - mx); lg[tid][e] = p; s += p; }
        const float inv = 1.f / s;
        for (int k = 0; k < KTOP; k++) {
            float best = -1.f; int bi = 0;
            for (int e = 0; e < NE; e++) { float v = lg[tid][e]; if (v > best) { best = v; bi = e; } }
            lg[tid][bi] = -2.f;
            g_tok_e[(t0 + tid) * KTOP + k] = bi;
            g_tok_w[(t0 + tid) * KTOP + k] = best * inv;
            atomicAdd(&g_cnt[bi], 1);
        }
    }
}

__global__ void k_scan() {
    if (threadIdx.x == 0) {
        int o = 0;
        for (int e = 0; e < NE; e++) { g_off[e] = o; o += g_cnt[e]; }
        g_off[NE] = o;
    }
}

__global__ void k_scatter() {
    const int t = blockIdx.x * 256 + threadIdx.x;
    if (t < NT) {
        for (int k = 0; k < KTOP; k++) {
            const int e = g_tok_e[t * KTOP + k];
            const int p = g_off[e] + atomicAdd(&g_cur[e], 1);
            g_pair_tok[p] = t;
            g_pair_w[p] = g_tok_w[t * KTOP + k];
        }
    }
}

// ---------------- shared up: g_Bsh = silu(X@W1s) * (X@W3s) ----------------
// block tile 128x64, BK=16, dual weights, 8 warps (4x2) -> warp tile 32x32
__global__ __launch_bounds__(256) void k_shared_up(const float* __restrict__ x,
                                                   const float* __restrict__ w1,
                                                   const float* __restrict__ w3) {
    __shared__ __align__(16) float As[STAGES][128][20];
    __shared__ __align__(16) float B1s[STAGES][16][72];
    __shared__ __align__(16) float B3s[STAGES][16][72];

    const int tid = threadIdx.x;
    const int m0 = blockIdx.y * 128;
    const int n0 = blockIdx.x * 64;
    const int lane = tid & 31, warp = tid >> 5;
    const int g = lane >> 2, tg = lane & 3;
    const int wm = (warp >> 1) * 32, wn = (warp & 1) * 32;
    const int ar = tid >> 2, ac = (tid & 3) * 4;
    const int br = tid >> 4, bc = (tid & 15) * 4;

    float c1[2][4][4], c3[2][4][4];
    #pragma unroll
    for (int i = 0; i < 2; i++)
        #pragma unroll
        for (int j = 0; j < 4; j++)
            #pragma unroll
            for (int l = 0; l < 4; l++) { c1[i][j][l] = 0.f; c3[i][j][l] = 0.f; }

    auto load_stage = [&](int st, int kk) {
        const int k0 = kk * 16;
        cpa16(&As[st][ar][ac],      x  + (size_t)(m0 + ar) * NH + k0 + ac);
        cpa16(&As[st][ar + 64][ac], x  + (size_t)(m0 + ar + 64) * NH + k0 + ac);
        cpa16(&B1s[st][br][bc],     w1 + (size_t)(k0 + br) * NS + n0 + bc);
        cpa16(&B3s[st][br][bc],     w3 + (size_t)(k0 + br) * NS + n0 + bc);
    };
    #pragma unroll
    for (int s = 0; s < STAGES - 1; s++) { load_stage(s, s); cpcommit(); }

    const int NKI = NH / 16;
    for (int kk = 0; kk < NKI; ++kk) {
        const int st = kk & (STAGES - 1);
        cpwaitS2();
        __syncthreads();
        #pragma unroll
        for (int k8 = 0; k8 < 2; k8++) {
            const int kb = k8 * 8;
            uint32_t a[2][4];
            #pragma unroll
            for (int im = 0; im < 2; im++) {
                const int r = wm + im * 16;
                a[im][0] = f2tf(As[st][r + g    ][kb + tg    ]);
                a[im][1] = f2tf(As[st][r + g + 8][kb + tg    ]);
                a[im][2] = f2tf(As[st][r + g    ][kb + tg + 4]);
                a[im][3] = f2tf(As[st][r + g + 8][kb + tg + 4]);
            }
            #pragma unroll
            for (int in = 0; in < 4; in++) {
                const int cn = wn + in * 8 + g;
                uint32_t b1v[2], b3v[2];
                b1v[0] = f2tf(B1s[st][kb + tg    ][cn]);
                b1v[1] = f2tf(B1s[st][kb + tg + 4][cn]);
                b3v[0] = f2tf(B3s[st][kb + tg    ][cn]);
                b3v[1] = f2tf(B3s[st][kb + tg + 4][cn]);
                #pragma unroll
                for (int im = 0; im < 2; im++) {
                    mma8(c1[im][in], a[im], b1v);
                    mma8(c3[im][in], a[im], b3v);
                }
            }
        }
        if (kk + STAGES - 1 < NKI) load_stage((kk + STAGES - 1) & (STAGES - 1), kk + STAGES - 1);
        cpcommit();
    }

    #pragma unroll
    for (int im = 0; im < 2; im++) {
        const int row = m0 + wm + im * 16 + g;
        #pragma unroll
        for (int in = 0; in < 4; in++) {
            const int col = n0 + wn + in * 8 + tg * 2;
            float v0 = silu_mul(c1[im][in][0], c3[im][in][0]);
            float v1 = silu_mul(c1[im][in][1], c3[im][in][1]);
            float v2 = silu_mul(c1[im][in][2], c3[im][in][2]);
            float v3 = silu_mul(c1[im][in][3], c3[im][in][3]);
            *reinterpret_cast<float2*>(&g_Bsh[(size_t)row * NS + col])       = make_float2(v0, v1);
            *reinterpret_cast<float2*>(&g_Bsh[(size_t)(row + 8) * NS + col]) = make_float2(v2, v3);
        }
    }
}

// ---------------- shared down: out = sg[t] * (g_Bsh @ W2s) ----------------
__global__ __launch_bounds__(256) void k_shared_down(float* __restrict__ out,
                                                     const float* __restrict__ w2) {
    __shared__ __align__(16) float As[STAGES][128][20];
    __shared__ __align__(16) float Bs[STAGES][16][72];

    const int tid = threadIdx.x;
    const int m0 = blockIdx.y * 128;
    const int n0 = blockIdx.x * 64;
    const int lane = tid & 31, warp = tid >> 5;
    const int g = lane >> 2, tg = lane & 3;
    const int wm = (warp >> 1) * 32, wn = (warp & 1) * 32;
    const int ar = tid >> 2, ac = (tid & 3) * 4;
    const int br = tid >> 4, bc = (tid & 15) * 4;

    float c[2][4][4];
    #pragma unroll
    for (int i = 0; i < 2; i++)
        #pragma unroll
        for (int j = 0; j < 4; j++)
            #pragma unroll
            for (int l = 0; l < 4; l++) c[i][j][l] = 0.f;

    auto load_stage = [&](int st, int kk) {
        const int k0 = kk * 16;
        cpa16(&As[st][ar][ac],      g_Bsh + (size_t)(m0 + ar) * NS + k0 + ac);
        cpa16(&As[st][ar + 64][ac], g_Bsh + (size_t)(m0 + ar + 64) * NS + k0 + ac);
        cpa16(&Bs[st][br][bc],      w2 + (size_t)(k0 + br) * NH + n0 + bc);
    };
    #pragma unroll
    for (int s = 0; s < STAGES - 1; s++) { load_stage(s, s); cpcommit(); }

    const int NKI = NS / 16;
    for (int kk = 0; kk < NKI; ++kk) {
        const int st = kk & (STAGES - 1);
        cpwaitS2();
        __syncthreads();
        #pragma unroll
        for (int k8 = 0; k8 < 2; k8++) {
            const int kb = k8 * 8;
            uint32_t a[2][4];
            #pragma unroll
            for (int im = 0; im < 2; im++) {
                const int r = wm + im * 16;
                a[im][0] = f2tf(As[st][r + g    ][kb + tg    ]);
                a[im][1] = f2tf(As[st][r + g + 8][kb + tg    ]);
                a[im][2] = f2tf(As[st][r + g    ][kb + tg + 4]);
                a[im][3] = f2tf(As[st][r + g + 8][kb + tg + 4]);
            }
            #pragma unroll
            for (int in = 0; in < 4; in++) {
                const int cn = wn + in * 8 + g;
                uint32_t bv[2];
                bv[0] = f2tf(Bs[st][kb + tg    ][cn]);
                bv[1] = f2tf(Bs[st][kb + tg + 4][cn]);
                #pragma unroll
                for (int im = 0; im < 2; im++) mma8(c[im][in], a[im], bv);
            }
        }
        if (kk + STAGES - 1 < NKI) load_stage((kk + STAGES - 1) & (STAGES - 1), kk + STAGES - 1);
        cpcommit();
    }

    #pragma unroll
    for (int im = 0; im < 2; im++) {
        const int row = m0 + wm + im * 16 + g;
        const float s0 = g_sg[row], s1 = g_sg[row + 8];
        #pragma unroll
        for (int in = 0; in < 4; in++) {
            const int col = n0 + wn + in * 8 + tg * 2;
            *reinterpret_cast<float2*>(&out[(size_t)row * NH + col])       = make_float2(s0 * c[im][in][0], s0 * c[im][in][1]);
            *reinterpret_cast<float2*>(&out[(size_t)(row + 8) * NH + col]) = make_float2(s1 * c[im][in][2], s1 * c[im][in][3]);
        }
    }
}

// ---------------- routed up: g_Abuf[pair] = silu(Xe@w1e) * (Xe@w3e) ----------------
// block tile 64x64, dual weights, 8 warps (4x2) -> warp tile 16x32
__global__ __launch_bounds__(256) void k_moe_up(const float* __restrict__ x,
                                                const float* __restrict__ w1,
                                                const float* __restrict__ w3) {
    const int e = blockIdx.y;
    const int seg0 = g_off[e];
    const int ne = g_off[e + 1] - seg0;
    const int m0 = blockIdx.z * 64;
    if (m0 >= ne) return;
    const int n0 = blockIdx.x * 64;

    __shared__ __align__(16) float As[STAGES][64][20];
    __shared__ __align__(16) float B1s[STAGES][16][72];
    __shared__ __align__(16) float B3s[STAGES][16][72];

    const int tid = threadIdx.x;
    const int lane = tid & 31, warp = tid >> 5;
    const int g = lane >> 2, tg = lane & 3;
    const int wm = (warp >> 1) * 16, wn = (warp & 1) * 32;
    const int ar = tid >> 2, ac = (tid & 3) * 4;
    const int br = tid >> 4, bc = (tid & 15) * 4;

    const int prow = m0 + ar;
    const float* arow = x + (size_t)g_pair_tok[seg0 + (prow < ne ? prow : 0)] * NH;
    const float* w1e = w1 + (size_t)e * NH * NI;
    const float* w3e = w3 + (size_t)e * NH * NI;

    float c1[4][4], c3[4][4];
    #pragma unroll
    for (int j = 0; j < 4; j++)
        #pragma unroll
        for (int l = 0; l < 4; l++) { c1[j][l] = 0.f; c3[j][l] = 0.f; }

    auto load_stage = [&](int st, int kk) {
        const int k0 = kk * 16;
        cpa16(&As[st][ar][ac], arow + k0 + ac);
        cpa16(&B1s[st][br][bc], w1e + (size_t)(k0 + br) * NI + n0 + bc);
        cpa16(&B3s[st][br][bc], w3e + (size_t)(k0 + br) * NI + n0 + bc);
    };
    #pragma unroll
    for (int s = 0; s < STAGES - 1; s++) { load_stage(s, s); cpcommit(); }

    const int NKI = NH / 16;
    for (int kk = 0; kk < NKI; ++kk) {
        const int st = kk & (STAGES - 1);
        cpwaitS2();
        __syncthreads();
        #pragma unroll
        for (int k8 = 0; k8 < 2; k8++) {
            const int kb = k8 * 8;
            uint32_t a[4];
            a[0] = f2tf(As[st][wm + g    ][kb + tg    ]);
            a[1] = f2tf(As[st][wm + g + 8][kb + tg    ]);
            a[2] = f2tf(As[st][wm + g    ][kb + tg + 4]);
            a[3] = f2tf(As[st][wm + g + 8][kb + tg + 4]);
            #pragma unroll
            for (int in = 0; in < 4; in++) {
                const int cn = wn + in * 8 + g;
                uint32_t b1v[2], b3v[2];
                b1v[0] = f2tf(B1s[st][kb + tg    ][cn]);
                b1v[1] = f2tf(B1s[st][kb + tg + 4][cn]);
                b3v[0] = f2tf(B3s[st][kb + tg    ][cn]);
                b3v[1] = f2tf(B3s[st][kb + tg + 4][cn]);
                mma8(c1[in], a, b1v);
                mma8(c3[in], a, b3v);
            }
        }
        if (kk + STAGES - 1 < NKI) load_stage((kk + STAGES - 1) & (STAGES - 1), kk + STAGES - 1);
        cpcommit();
    }

    const int lr = wm + g;
    const bool vr0 = (m0 + lr) < ne;
    const bool vr1 = (m0 + lr + 8) < ne;
    float* o0 = &g_Abuf[(size_t)(seg0 + m0 + lr) * NI];
    float* o1 = o0 + (size_t)8 * NI;
    #pragma unroll
    for (int in = 0; in < 4; in++) {
        const int col = n0 + wn + in * 8 + tg * 2;
        if (vr0) *reinterpret_cast<float2*>(o0 + col) =
            make_float2(silu_mul(c1[in][0], c3[in][0]), silu_mul(c1[in][1], c3[in][1]));
        if (vr1) *reinterpret_cast<float2*>(o1 + col) =
            make_float2(silu_mul(c1[in][2], c3[in][2]), silu_mul(c1[in][3], c3[in][3]));
    }
}

// ---------------- routed down: out[tok] += pair_w * (Abuf_seg @ w2e) ----------------
__global__ __launch_bounds__(256) void k_moe_down(float* __restrict__ out,
                                                  const float* __restrict__ w2) {
    const int e = blockIdx.y;
    const int seg0 = g_off[e];
    const int ne = g_off[e + 1] - seg0;
    const int m0 = blockIdx.z * 64;
    if (m0 >= ne) return;
    const int n0 = blockIdx.x * 64;

    __shared__ __align__(16) float As[STAGES][64][20];
    __shared__ __align__(16) float Bs[STAGES][16][72];

    const int tid = threadIdx.x;
    const int lane = tid & 31, warp = tid >> 5;
    const int g = lane >> 2, tg = lane & 3;
    const int wm = (warp >> 1) * 16, wn = (warp & 1) * 32;
    const int ar = tid >> 2, ac = (tid & 3) * 4;
    const int br = tid >> 4, bc = (tid & 15) * 4;

    int aidx = seg0 + m0 + ar;
    if (aidx > NPAIR - 1) aidx = NPAIR - 1;
    const float* arow = g_Abuf + (size_t)aidx * NI;
    const float* w2e = w2 + (size_t)e * NI * NH;

    float c[4][4];
    #pragma unroll
    for (int j = 0; j < 4; j++)
        #pragma unroll
        for (int l = 0; l < 4; l++) c[j][l] = 0.f;

    auto load_stage = [&](int st, int kk) {
        const int k0 = kk * 16;
        cpa16(&As[st][ar][ac], arow + k0 + ac);
        cpa16(&Bs[st][br][bc], w2e + (size_t)(k0 + br) * NH + n0 + bc);
    };
    #pragma unroll
    for (int s = 0; s < STAGES - 1; s++) { load_stage(s, s); cpcommit(); }

    const int NKI = NI / 16;
    for (int kk = 0; kk < NKI; ++kk) {
        const int st = kk & (STAGES - 1);
        cpwaitS2();
        __syncthreads();
        #pragma unroll
        for (int k8 = 0; k8 < 2; k8++) {
            const int kb = k8 * 8;
            uint32_t a[4];
            a[0] = f2tf(As[st][wm + g    ][kb + tg    ]);
            a[1] = f2tf(As[st][wm + g + 8][kb + tg    ]);
            a[2] = f2tf(As[st][wm + g    ][kb + tg + 4]);
            a[3] = f2tf(As[st][wm + g + 8][kb + tg + 4]);
            #pragma unroll
            for (int in = 0; in < 4; in++) {
                const int cn = wn + in * 8 + g;
                uint32_t bv[2];
                bv[0] = f2tf(Bs[st][kb + tg    ][cn]);
                bv[1] = f2tf(Bs[st][kb + tg + 4][cn]);
                mma8(c[in], a, bv);
            }
        }
        if (kk + STAGES - 1 < NKI) load_stage((kk + STAGES - 1) & (STAGES - 1), kk + STAGES - 1);
        cpcommit();
    }

    const int lr = wm + g;
    if (m0 + lr < ne) {
        const int p = seg0 + m0 + lr;
        const int t = g_pair_tok[p];
        const float w = g_pair_w[p];
        float* orow = out + (size_t)t * NH;
        #pragma unroll
        for (int in = 0; in < 4; in++) {
            const int col = n0 + wn + in * 8 + tg * 2;
            atomicAdd(orow + col,     w * c[in][0]);
            atomicAdd(orow + col + 1, w * c[in][1]);
        }
    }
    if (m0 + lr + 8 < ne) {
        const int p = seg0 + m0 + lr + 8;
        const int t = g_pair_tok[p];
        const float w = g_pair_w[p];
        float* orow = out + (size_t)t * NH;
        #pragma unroll
        for (int in = 0; in < 4; in++) {
            const int col = n0 + wn + in * 8 + tg * 2;
            atomicAdd(orow + col,     w * c[in][2]);
            atomicAdd(orow + col + 1, w * c[in][3]);
        }
    }
}

// ---------------- launch ----------------
extern "C" void kernel_launch(void* const* d_in, const int* in_sizes, int n_in,
                              void* d_out, int out_size) {
    const float* x   = (const float*)d_in[0];
    const float* gw  = (const float*)d_in[1];
    const float* w1  = (const float*)d_in[2];
    const float* w3  = (const float*)d_in[3];
    const float* w2  = (const float*)d_in[4];
    const float* sw1 = (const float*)d_in[5];
    const float* sw3 = (const float*)d_in[6];
    const float* sw2 = (const float*)d_in[7];
    const float* sgw = (const float*)d_in[8];
    float* out = (float*)d_out;

    k_init<<<1, 64>>>();
    k_router<<<NT / 4, 256>>>(x, gw, sgw);
    k_scan<<<1, 32>>>();
    k_scatter<<<2, 256>>>();

    // shared expert: up (fused gate/up + silu), then down (+sigmoid gate) writes out
    k_shared_up<<<dim3(NS / 64, NT / 128), 256>>>(x, sw1, sw3);
    // routed experts: up (fused, gathered rows)
    k_moe_up<<<dim3(NI / 64, NE, 8), 256>>>(x, w1, w3);
    // shared down writes every out element (out is poisoned before timing)
    k_shared_down<<<dim3(NH / 64, NT / 128), 256>>>(out, sw2);
    // routed down accumulates into out via atomics
    k_moe_down<<<dim3(NH / 64, NE, 8), 256>>>(out, w2);
}

// round 12
// speedup vs baseline: 1.3415x; 1.1762x over previous
#include <cuda_runtime.h>
#include <cuda_fp16.h>
#include <cstdint>
#include <math.h>

#define NT 512
#define NH 2048
#define NE 60
#define NI 1408
#define NS 5632
#define KTOP 4
#define NPAIR (NT*KTOP)

// ---------------- device scratch (static, no allocations) ----------------
__device__ __align__(16) __half g_Ab[NPAIR * NI];   // routed act, fp16
__device__ __align__(16) __half g_Bs[NT * NS];      // shared act, fp16
__device__ __align__(16) __half g_xh[NT * NH];      // hidden states, fp16
__device__ int   g_pair_tok[NPAIR];
__device__ float g_pair_w[NPAIR];
__device__ int   g_cnt[NE];
__device__ int   g_off[NE + 1];
__device__ int   g_cur[NE];
__device__ float g_sg[NT];
__device__ int   g_tok_e[NT * KTOP];
__device__ float g_tok_w[NT * KTOP];

// ---------------- helpers ----------------
__device__ __forceinline__ uint32_t s2u(const void* p) { return (uint32_t)__cvta_generic_to_shared(p); }
__device__ __forceinline__ void cpa16(uint32_t s, const void* g) {
    asm volatile("cp.async.cg.shared.global [%0], [%1], 16;" :: "r"(s), "l"(g));
}
__device__ __forceinline__ void cpcommit() { asm volatile("cp.async.commit_group;"); }
__device__ __forceinline__ void cpwait1()  { asm volatile("cp.async.wait_group 1;"); }
__device__ __forceinline__ float silu_mul(float h1, float h3) { return h3 * (h1 / (1.0f + expf(-h1))); }
__device__ __forceinline__ uint32_t pack_h2(float lo, float hi) {
    __half2 h = __floats2half2_rn(lo, hi);           // x = lo (low 16 bits), y = hi
    return *reinterpret_cast<uint32_t*>(&h);
}
__device__ __forceinline__ void mma16(float* c, const uint32_t* a, uint32_t b0, uint32_t b1) {
    asm volatile(
        "mma.sync.aligned.m16n8k16.row.col.f32.f16.f16.f32 "
        "{%0,%1,%2,%3}, {%4,%5,%6,%7}, {%8,%9}, {%0,%1,%2,%3};"
        : "+f"(c[0]), "+f"(c[1]), "+f"(c[2]), "+f"(c[3])
        : "r"(a[0]), "r"(a[1]), "r"(a[2]), "r"(a[3]), "r"(b0), "r"(b1));
}

// ---------------- small kernels ----------------
__global__ void k_init() { int i = threadIdx.x; if (i < NE) { g_cnt[i] = 0; g_cur[i] = 0; } }

__global__ __launch_bounds__(256) void k_tohalf(const float* __restrict__ x) {
    int i = blockIdx.x * 256 + threadIdx.x;          // NT*NH/4 threads
    float4 v = reinterpret_cast<const float4*>(x)[i];
    uint2 o; o.x = pack_h2(v.x, v.y); o.y = pack_h2(v.z, v.w);
    reinterpret_cast<uint2*>(g_xh)[i] = o;
}

__global__ __launch_bounds__(256) void k_router(const float* __restrict__ x,
                                                const float* __restrict__ gw,
                                                const float* __restrict__ sgw) {
    __shared__ __align__(16) float xs[4][NH];
    __shared__ float lg[4][64];
    const int t0 = blockIdx.x * 4, tid = threadIdx.x;
    const float4* xg = reinterpret_cast<const float4*>(x + (size_t)t0 * NH);
    float4* xv = reinterpret_cast<float4*>(&xs[0][0]);
    for (int i = tid; i < 4 * NH / 4; i += 256) xv[i] = xg[i];
    __syncthreads();
    if (tid < 4 * 61) {
        const int tl = tid / 61, e = tid % 61;
        float acc = 0.f;
        if (e < NE) {
            #pragma unroll 8
            for (int h = 0; h < NH; h++) acc += xs[tl][h] * gw[h * NE + e];
            lg[tl][e] = acc;
        } else {
            #pragma unroll 8
            for (int h = 0; h < NH; h++) acc += xs[tl][h] * sgw[h];
            g_sg[t0 + tl] = 1.f / (1.f + expf(-acc));
        }
    }
    __syncthreads();
    if (tid < 4) {
        float mx = -1e30f;
        for (int e = 0; e < NE; e++) mx = fmaxf(mx, lg[tid][e]);
        float s = 0.f;
        for (int e = 0; e < NE; e++) { float p = expf(lg[tid][e] - mx); lg[tid][e] = p; s += p; }
        const float inv = 1.f / s;
        for (int k = 0; k < KTOP; k++) {
            float best = -1.f; int bi = 0;
            for (int e = 0; e < NE; e++) { float v = lg[tid][e]; if (v > best) { best = v; bi = e; } }
            lg[tid][bi] = -2.f;
            g_tok_e[(t0 + tid) * KTOP + k] = bi;
            g_tok_w[(t0 + tid) * KTOP + k] = best * inv;
            atomicAdd(&g_cnt[bi], 1);
        }
    }
}

__global__ void k_scan() {
    if (threadIdx.x == 0) {
        int o = 0;
        for (int e = 0; e < NE; e++) { g_off[e] = o; o += g_cnt[e]; }
        g_off[NE] = o;
    }
}

__global__ void k_scatter() {
    const int t = blockIdx.x * 256 + threadIdx.x;
    if (t < NT) {
        for (int k = 0; k < KTOP; k++) {
            const int e = g_tok_e[t * KTOP + k];
            const int p = g_off[e] + atomicAdd(&g_cur[e], 1);
            g_pair_tok[p] = t;
            g_pair_w[p] = g_tok_w[t * KTOP + k];
        }
    }
}

// ================= unified fp16 mma.sync GEMM =================
// Block BM x 128, warp tile 32x32, BK=32, 3-stage cp.async ring.
// A: fp16 activations (pre-converted, loaded as half2 pairs — no cvt in loop).
// B: fp32 weights in smem, cvt to half2 at fragment load.
// EPI: 0 = silu(D1)*D3 -> half act buffer (dual B)
//      1 = sigmoid-gate-scaled store -> out
//      2 = pair_w-weighted atomicAdd -> out
template<int EPI, int ROUTED, int BM, int KD, int BSTR>
__global__ void __launch_bounds__(BM * 4) k_g(const float* __restrict__ B1p,
                                              const float* __restrict__ B3p,
                                              float* __restrict__ O) {
    constexpr int DUAL = (EPI == 0) ? 1 : 0;
    constexpr int THREADS = BM * 4;
    constexpr int ABYTES = BM * 80;                  // 32 half (64B) + 16B pad per row
    constexpr int STG = ABYTES + 16896 * (1 + DUAL); // B: 32 rows x 528B
    extern __shared__ __align__(16) char smem[];
    const int tid = threadIdx.x;
    const int n0 = blockIdx.x * 128;
    int seg0 = 0, ne = 1 << 30, m0;
    if (ROUTED) {
        const int e = blockIdx.y;
        seg0 = g_off[e]; ne = g_off[e + 1] - seg0;
        m0 = blockIdx.z * BM;
        if (m0 >= ne) return;
        B1p += (size_t)e * KD * BSTR;
        if (DUAL) B3p += (size_t)e * KD * BSTR;
    } else m0 = blockIdx.y * BM;

    // A source row (half)
    const int arow_l = tid >> 2, achk = tid & 3;
    int arow = m0 + arow_l;
    if (ROUTED && arow >= ne) arow = ne - 1;
    const __half* aptr;
    if (EPI == 0)      aptr = g_xh + (size_t)(ROUTED ? g_pair_tok[seg0 + arow] : arow) * NH;
    else if (EPI == 1) aptr = g_Bs + (size_t)arow * NS;
    else               aptr = g_Ab + (size_t)(seg0 + arow) * NI;
    aptr += achk * 8;

    const uint32_t sb = s2u(smem);
    const uint32_t adst = sb + arow_l * 80 + achk * 16;

    auto load_stage = [&](int s, int kk) {
        const int k0 = kk * 32;
        cpa16(adst + s * STG, aptr + k0);
        constexpr int NB = 1024 * (1 + DUAL) / THREADS;
        #pragma unroll
        for (int it = 0; it < NB; it++) {
            const int idx = tid + it * THREADS;
            const int mat = idx >> 10, row = (idx >> 5) & 31, chk = idx & 31;
            const float* src = ((DUAL && mat) ? B3p : B1p) + (size_t)(k0 + row) * BSTR + n0 + chk * 4;
            cpa16(sb + s * STG + ABYTES + mat * 16896 + row * 528 + chk * 16, src);
        }
    };
    load_stage(0, 0); cpcommit();
    load_stage(1, 1); cpcommit();

    const int lane = tid & 31, w = tid >> 5;
    const int g = lane >> 2, tg = lane & 3;
    const int wm = (w >> 2) * 32, wn = (w & 3) * 32;
    float c1[2][4][4], c3[2][4][4];
    #pragma unroll
    for (int im = 0; im < 2; im++)
        #pragma unroll
        for (int in = 0; in < 4; in++)
            #pragma unroll
            for (int q = 0; q < 4; q++) { c1[im][in][q] = 0.f; c3[im][in][q] = 0.f; }

    const int NK = KD / 32;
    for (int kk = 0; kk < NK; kk++) {
        const int s = kk % 3;
        cpwait1();
        __syncthreads();
        const char* A0 = smem + s * STG;
        const char* Bb = A0 + ABYTES;
        #pragma unroll
        for (int h = 0; h < 2; h++) {
            uint32_t a[2][4];
            #pragma unroll
            for (int im = 0; im < 2; im++) {
                const char* ar0 = A0 + (wm + im * 16 + g) * 80 + (h * 8 + tg) * 4;
                const char* ar1 = ar0 + 8 * 80;
                a[im][0] = *(const uint32_t*)ar0;
                a[im][1] = *(const uint32_t*)ar1;
                a[im][2] = *(const uint32_t*)(ar0 + 16);
                a[im][3] = *(const uint32_t*)(ar1 + 16);
            }
            #pragma unroll
            for (int in = 0; in < 4; in++) {
                const char* p0 = Bb + (h * 16 + 2 * tg) * 528 + (wn + in * 8 + g) * 4;
                uint32_t b0 = pack_h2(*(const float*)p0,            *(const float*)(p0 + 528));
                uint32_t b1 = pack_h2(*(const float*)(p0 + 8 * 528), *(const float*)(p0 + 9 * 528));
                mma16(c1[0][in], a[0], b0, b1);
                mma16(c1[1][in], a[1], b0, b1);
                if (DUAL) {
                    const char* q0 = p0 + 16896;
                    uint32_t d0 = pack_h2(*(const float*)q0,            *(const float*)(q0 + 528));
                    uint32_t d1 = pack_h2(*(const float*)(q0 + 8 * 528), *(const float*)(q0 + 9 * 528));
                    mma16(c3[0][in], a[0], d0, d1);
                    mma16(c3[1][in], a[1], d0, d1);
                }
            }
        }
        if (kk + 2 < NK) load_stage((kk + 2) % 3, kk + 2);
        cpcommit();
    }

    // ---------------- epilogue ----------------
    #pragma unroll
    for (int im = 0; im < 2; im++) {
        const int mr0 = m0 + wm + im * 16 + g, mr1 = mr0 + 8;
        if (EPI == 1) {
            const float s0 = g_sg[mr0], s1 = g_sg[mr1];
            #pragma unroll
            for (int in = 0; in < 4; in++) {
                const int col = n0 + wn + in * 8 + tg * 2;
                *reinterpret_cast<float2*>(&O[(size_t)mr0 * NH + col]) =
                    make_float2(s0 * c1[im][in][0], s0 * c1[im][in][1]);
                *reinterpret_cast<float2*>(&O[(size_t)mr1 * NH + col]) =
                    make_float2(s1 * c1[im][in][2], s1 * c1[im][in][3]);
            }
        } else if (EPI == 0) {
            #pragma unroll
            for (int in = 0; in < 4; in++) {
                const int col = n0 + wn + in * 8 + tg * 2;
                if (!ROUTED || mr0 < ne) {
                    uint32_t v = pack_h2(silu_mul(c1[im][in][0], c3[im][in][0]),
                                         silu_mul(c1[im][in][1], c3[im][in][1]));
                    __half* dst = ROUTED ? (g_Ab + (size_t)(seg0 + mr0) * NI + col)
                                         : (g_Bs + (size_t)mr0 * NS + col);
                    *reinterpret_cast<uint32_t*>(dst) = v;
                }
                if (!ROUTED || mr1 < ne) {
                    uint32_t v = pack_h2(silu_mul(c1[im][in][2], c3[im][in][2]),
                                         silu_mul(c1[im][in][3], c3[im][in][3]));
                    __half* dst = ROUTED ? (g_Ab + (size_t)(seg0 + mr1) * NI + col)
                                         : (g_Bs + (size_t)mr1 * NS + col);
                    *reinterpret_cast<uint32_t*>(dst) = v;
                }
            }
        } else {
            if (mr0 < ne) {
                const int p = seg0 + mr0; const float wv = g_pair_w[p];
                float* orow = O + (size_t)g_pair_tok[p] * NH;
                #pragma unroll
                for (int in = 0; in < 4; in++) {
                    const int col = n0 + wn + in * 8 + tg * 2;
                    atomicAdd(orow + col,     wv * c1[im][in][0]);
                    atomicAdd(orow + col + 1, wv * c1[im][in][1]);
                }
            }
            if (mr1 < ne) {
                const int p = seg0 + mr1; const float wv = g_pair_w[p];
                float* orow = O + (size_t)g_pair_tok[p] * NH;
                #pragma unroll
                for (int in = 0; in < 4; in++) {
                    const int col = n0 + wn + in * 8 + tg * 2;
                    atomicAdd(orow + col,     wv * c1[im][in][2]);
                    atomicAdd(orow + col + 1, wv * c1[im][in][3]);
                }
            }
        }
    }
}

// ---------------- launch ----------------
extern "C" void kernel_launch(void* const* d_in, const int* in_sizes, int n_in,
                              void* d_out, int out_size) {
    const float* x   = (const float*)d_in[0];
    const float* gw  = (const float*)d_in[1];
    const float* w1  = (const float*)d_in[2];
    const float* w3  = (const float*)d_in[3];
    const float* w2  = (const float*)d_in[4];
    const float* sw1 = (const float*)d_in[5];
    const float* sw3 = (const float*)d_in[6];
    const float* sw2 = (const float*)d_in[7];
    const float* sgw = (const float*)d_in[8];
    float* out = (float*)d_out;

    const int SM_SU = 3 * (128 * 80 + 2 * 16896);  // 132096  shared_up
    const int SM_MU = 3 * (64 * 80 + 2 * 16896);   // 116736  moe_up
    const int SM_DN = 3 * (64 * 80 + 16896);       // 66048   down kernels
    cudaFuncSetAttribute(k_g<0,0,128,NH,NS>, cudaFuncAttributeMaxDynamicSharedMemorySize, SM_SU);
    cudaFuncSetAttribute(k_g<0,1,64,NH,NI>,  cudaFuncAttributeMaxDynamicSharedMemorySize, SM_MU);
    cudaFuncSetAttribute(k_g<1,0,64,NS,NH>,  cudaFuncAttributeMaxDynamicSharedMemorySize, SM_DN);
    cudaFuncSetAttribute(k_g<2,1,64,NI,NH>,  cudaFuncAttributeMaxDynamicSharedMemorySize, SM_DN);

    k_init<<<1, 64>>>();
    k_tohalf<<<NT * NH / 4 / 256, 256>>>(x);
    k_router<<<NT / 4, 256>>>(x, gw, sgw);
    k_scan<<<1, 32>>>();
    k_scatter<<<2, 256>>>();

    // shared up: g_Bs = silu(xh@sw1)*(xh@sw3)        [fp16 out]
    k_g<0,0,128,NH,NS><<<dim3(NS/128, NT/128), 512, SM_SU>>>(sw1, sw3, nullptr);
    // routed up: g_Ab = silu(gather(xh)@w1e)*(gather(xh)@w3e)
    k_g<0,1,64,NH,NI><<<dim3(NI/128, NE, 8), 256, SM_MU>>>(w1, w3, nullptr);
    // shared down: out = sg * (g_Bs @ sw2)           (writes every element)
    k_g<1,0,64,NS,NH><<<dim3(NH/128, NT/64), 256, SM_DN>>>(sw2, nullptr, out);
    // routed down: out += pair_w * (g_Ab seg @ w2e)
    k_g<2,1,64,NI,NH><<<dim3(NH/128, NE, 8), 256, SM_DN>>>(w2, nullptr, out);
}

// round 15
// speedup vs baseline: 1.4611x; 1.0891x over previous
#include <cuda_runtime.h>
#include <cuda_fp16.h>
#include <cstdint>
#include <math.h>

#define NT 512
#define NH 2048
#define NE 60
#define NI 1408
#define NS 5632
#define KTOP 4
#define NPAIR (NT*KTOP)

// ---------------- device scratch (static, no allocations) ----------------
__device__ __align__(16) __half g_Ab[NPAIR * NI];   // routed act, fp16
__device__ __align__(16) __half g_Bs[NT * NS];      // shared act, fp16
__device__ __align__(16) __half g_xh[NT * NH];      // hidden states, fp16
__device__ int   g_pair_tok[NPAIR];
__device__ float g_pair_w[NPAIR];
__device__ int   g_cnt[NE];
__device__ int   g_off[NE + 1];
__device__ int   g_cur[NE];
__device__ float g_sg[NT];
__device__ int   g_tok_e[NT * KTOP];
__device__ float g_tok_w[NT * KTOP];

// ---------------- helpers ----------------
__device__ __forceinline__ uint32_t s2u(const void* p) { return (uint32_t)__cvta_generic_to_shared(p); }
__device__ __forceinline__ void cpa16(uint32_t s, const void* g) {
    asm volatile("cp.async.cg.shared.global [%0], [%1], 16;" :: "r"(s), "l"(g));
}
__device__ __forceinline__ void cpcommit() { asm volatile("cp.async.commit_group;"); }
__device__ __forceinline__ void cpwait1()  { asm volatile("cp.async.wait_group 1;"); }
__device__ __forceinline__ float silu_mul(float h1, float h3) { return h3 * (h1 / (1.0f + expf(-h1))); }
__device__ __forceinline__ uint32_t pack_h2(float lo, float hi) {
    __half2 h = __floats2half2_rn(lo, hi);
    return *reinterpret_cast<uint32_t*>(&h);
}
__device__ __forceinline__ void mma16(float* c, const uint32_t* a, uint32_t b0, uint32_t b1) {
    asm volatile(
        "mma.sync.aligned.m16n8k16.row.col.f32.f16.f16.f32 "
        "{%0,%1,%2,%3}, {%4,%5,%6,%7}, {%8,%9}, {%0,%1,%2,%3};"
        : "+f"(c[0]), "+f"(c[1]), "+f"(c[2]), "+f"(c[3])
        : "r"(a[0]), "r"(a[1]), "r"(a[2]), "r"(a[3]), "r"(b0), "r"(b1));
}
__device__ __forceinline__ void ldm4(uint32_t* a, uint32_t addr) {
    asm volatile("ldmatrix.sync.aligned.m8n8.x4.shared.b16 {%0,%1,%2,%3}, [%4];"
                 : "=r"(a[0]), "=r"(a[1]), "=r"(a[2]), "=r"(a[3]) : "r"(addr));
}

// ---------------- pre: x -> fp16, and reset routing counters ----------------
__global__ __launch_bounds__(256) void k_pre(const float* __restrict__ x) {
    if (blockIdx.x == 0 && threadIdx.x < NE) { g_cnt[threadIdx.x] = 0; g_cur[threadIdx.x] = 0; }
    int i = blockIdx.x * 256 + threadIdx.x;          // NT*NH/4 threads
    float4 v = reinterpret_cast<const float4*>(x)[i];
    uint2 o; o.x = pack_h2(v.x, v.y); o.y = pack_h2(v.z, v.w);
    reinterpret_cast<uint2*>(g_xh)[i] = o;
}

// ---------------- router ----------------
__global__ __launch_bounds__(256) void k_router(const float* __restrict__ x,
                                                const float* __restrict__ gw,
                                                const float* __restrict__ sgw) {
    __shared__ __align__(16) float xs[4][NH];
    __shared__ float lg[4][64];
    const int t0 = blockIdx.x * 4, tid = threadIdx.x;
    const float4* xg = reinterpret_cast<const float4*>(x + (size_t)t0 * NH);
    float4* xv = reinterpret_cast<float4*>(&xs[0][0]);
    for (int i = tid; i < 4 * NH / 4; i += 256) xv[i] = xg[i];
    __syncthreads();
    if (tid < 4 * 61) {
        const int tl = tid / 61, e = tid % 61;
        float acc = 0.f;
        if (e < NE) {
            #pragma unroll 8
            for (int h = 0; h < NH; h++) acc += xs[tl][h] * gw[h * NE + e];
            lg[tl][e] = acc;
        } else {
            #pragma unroll 8
            for (int h = 0; h < NH; h++) acc += xs[tl][h] * sgw[h];
            g_sg[t0 + tl] = 1.f / (1.f + expf(-acc));
        }
    }
    __syncthreads();
    if (tid < 4) {
        float mx = -1e30f;
        for (int e = 0; e < NE; e++) mx = fmaxf(mx, lg[tid][e]);
        float s = 0.f;
        for (int e = 0; e < NE; e++) { float p = expf(lg[tid][e] - mx); lg[tid][e] = p; s += p; }
        const float inv = 1.f / s;
        for (int k = 0; k < KTOP; k++) {
            float best = -1.f; int bi = 0;
            for (int e = 0; e < NE; e++) { float v = lg[tid][e]; if (v > best) { best = v; bi = e; } }
            lg[tid][bi] = -2.f;
            g_tok_e[(t0 + tid) * KTOP + k] = bi;
            g_tok_w[(t0 + tid) * KTOP + k] = best * inv;
            atomicAdd(&g_cnt[bi], 1);
        }
    }
}

// ---------------- fused scan + scatter (1 block) ----------------
__global__ __launch_bounds__(512) void k_scansc() {
    if (threadIdx.x == 0) {
        int o = 0;
        for (int e = 0; e < NE; e++) { g_off[e] = o; o += g_cnt[e]; }
        g_off[NE] = o;
    }
    __syncthreads();
    const int t = threadIdx.x;
    if (t < NT) {
        for (int k = 0; k < KTOP; k++) {
            const int e = g_tok_e[t * KTOP + k];
            const int p = g_off[e] + atomicAdd(&g_cur[e], 1);
            g_pair_tok[p] = t;
            g_pair_w[p] = g_tok_w[t * KTOP + k];
        }
    }
}

// ================= unified fp16 mma.sync GEMM =================
// Block BM x 128, warp tile 32x32, BK=32, STAGES-deep cp.async ring.
// A: fp16 activations via ldmatrix.x4. B: fp32 weights, cvt at fragment load.
// EPI: 0 = silu(D1)*D3 -> half act buffer (dual B); 1 = sigmoid-scaled store;
//      2 = pair_w-weighted atomicAdd.
template<int EPI, int ROUTED, int BM, int KD, int BSTR, int STAGES, int MINB>
__global__ void __launch_bounds__(BM * 4, MINB) k_g(const float* __restrict__ B1p,
                                                    const float* __restrict__ B3p,
                                                    float* __restrict__ O) {
    constexpr int DUAL = (EPI == 0) ? 1 : 0;
    constexpr int THREADS = BM * 4;
    constexpr int ABYTES = BM * 80;                  // 32 half (64B) + 16B pad per row
    constexpr int STG = ABYTES + 16896 * (1 + DUAL); // B: 32 rows x 528B each matrix
    extern __shared__ __align__(16) char smem[];
    const int tid = threadIdx.x;
    const int n0 = blockIdx.x * 128;
    int seg0 = 0, ne = 1 << 30, m0;
    if (ROUTED) {
        const int e = blockIdx.y;
        seg0 = g_off[e]; ne = g_off[e + 1] - seg0;
        m0 = blockIdx.z * BM;
        if (m0 >= ne) return;
        B1p += (size_t)e * KD * BSTR;
        if (DUAL) B3p += (size_t)e * KD * BSTR;
    } else m0 = blockIdx.y * BM;

    // A source row (half)
    const int arow_l = tid >> 2, achk = tid & 3;
    int arow = m0 + arow_l;
    if (ROUTED && arow >= ne) arow = ne - 1;
    const __half* aptr;
    if (EPI == 0)      aptr = g_xh + (size_t)(ROUTED ? g_pair_tok[seg0 + arow] : arow) * NH;
    else if (EPI == 1) aptr = g_Bs + (size_t)arow * NS;
    else               aptr = g_Ab + (size_t)(seg0 + arow) * NI;
    aptr += achk * 8;

    const uint32_t sb = s2u(smem);
    const uint32_t adst = sb + arow_l * 80 + achk * 16;

    auto load_stage = [&](int s, int kk) {
        const int k0 = kk * 32;
        cpa16(adst + s * STG, aptr + k0);
        constexpr int NB = 1024 * (1 + DUAL) / THREADS;
        #pragma unroll
        for (int it = 0; it < NB; it++) {
            const int idx = tid + it * THREADS;
            const int mat = idx >> 10, row = (idx >> 5) & 31, chk = idx & 31;
            const float* src = ((DUAL && mat) ? B3p : B1p) + (size_t)(k0 + row) * BSTR + n0 + chk * 4;
            cpa16(sb + s * STG + ABYTES + mat * 16896 + row * 528 + chk * 16, src);
        }
    };
    load_stage(0, 0); cpcommit();
    load_stage(1, 1); cpcommit();

    const int lane = tid & 31, w = tid >> 5;
    const int g = lane >> 2, tg = lane & 3;
    const int wm = (w >> 2) * 32, wn = (w & 3) * 32;
    // ldmatrix lane -> address base (row stride 80B): rows from groups, col halves from group>>1
    const int lmr = lane & 7, lmg = lane >> 3;
    const uint32_t a_lm_base = sb + (uint32_t)(wm + (lmg & 1) * 8 + lmr) * 80 + (uint32_t)(lmg >> 1) * 16;

    float c1[2][4][4], c3[2][4][4];
    #pragma unroll
    for (int im = 0; im < 2; im++)
        #pragma unroll
        for (int in = 0; in < 4; in++)
            #pragma unroll
            for (int q = 0; q < 4; q++) { c1[im][in][q] = 0.f; c3[im][in][q] = 0.f; }

    const int NK = KD / 32;
    for (int kk = 0; kk < NK; kk++) {
        const int s = kk % STAGES;
        cpwait1();
        __syncthreads();
        const char* Bb = smem + s * STG + ABYTES;
        #pragma unroll
        for (int h = 0; h < 2; h++) {
            uint32_t a[2][4];
            ldm4(a[0], a_lm_base + s * STG + h * 32);
            ldm4(a[1], a_lm_base + s * STG + 16 * 80 + h * 32);
            #pragma unroll
            for (int in = 0; in < 4; in++) {
                const char* p0 = Bb + (h * 16 + 2 * tg) * 528 + (wn + in * 8 + g) * 4;
                uint32_t b0 = pack_h2(*(const float*)p0,             *(const float*)(p0 + 528));
                uint32_t b1 = pack_h2(*(const float*)(p0 + 8 * 528), *(const float*)(p0 + 9 * 528));
                mma16(c1[0][in], a[0], b0, b1);
                mma16(c1[1][in], a[1], b0, b1);
                if (DUAL) {
                    const char* q0 = p0 + 16896;
                    uint32_t d0 = pack_h2(*(const float*)q0,             *(const float*)(q0 + 528));
                    uint32_t d1 = pack_h2(*(const float*)(q0 + 8 * 528), *(const float*)(q0 + 9 * 528));
                    mma16(c3[0][in], a[0], d0, d1);
                    mma16(c3[1][in], a[1], d0, d1);
                }
            }
        }
        if (STAGES == 2) __syncthreads();   // buffer kk+2 aliases kk: all readers must finish
        if (kk + 2 < NK) load_stage((kk + 2) % STAGES, kk + 2);
        cpcommit();
    }

    // ---------------- epilogue ----------------
    #pragma unroll
    for (int im = 0; im < 2; im++) {
        const int mr0 = m0 + wm + im * 16 + g, mr1 = mr0 + 8;
        if (EPI == 1) {
            const float s0 = g_sg[mr0], s1 = g_sg[mr1];
            #pragma unroll
            for (int in = 0; in < 4; in++) {
                const int col = n0 + wn + in * 8 + tg * 2;
                *reinterpret_cast<float2*>(&O[(size_t)mr0 * NH + col]) =
                    make_float2(s0 * c1[im][in][0], s0 * c1[im][in][1]);
                *reinterpret_cast<float2*>(&O[(size_t)mr1 * NH + col]) =
                    make_float2(s1 * c1[im][in][2], s1 * c1[im][in][3]);
            }
        } else if (EPI == 0) {
            #pragma unroll
            for (int in = 0; in < 4; in++) {
                const int col = n0 + wn + in * 8 + tg * 2;
                if (!ROUTED || mr0 < ne) {
                    uint32_t v = pack_h2(silu_mul(c1[im][in][0], c3[im][in][0]),
                                         silu_mul(c1[im][in][1], c3[im][in][1]));
                    __half* dst = ROUTED ? (g_Ab + (size_t)(seg0 + mr0) * NI + col)
                                         : (g_Bs + (size_t)mr0 * NS + col);
                    *reinterpret_cast<uint32_t*>(dst) = v;
                }
                if (!ROUTED || mr1 < ne) {
                    uint32_t v = pack_h2(silu_mul(c1[im][in][2], c3[im][in][2]),
                                         silu_mul(c1[im][in][3], c3[im][in][3]));
                    __half* dst = ROUTED ? (g_Ab + (size_t)(seg0 + mr1) * NI + col)
                                         : (g_Bs + (size_t)mr1 * NS + col);
                    *reinterpret_cast<uint32_t*>(dst) = v;
                }
            }
        } else {
            if (mr0 < ne) {
                const int p = seg0 + mr0; const float wv = g_pair_w[p];
                float* orow = O + (size_t)g_pair_tok[p] * NH;
                #pragma unroll
                for (int in = 0; in < 4; in++) {
                    const int col = n0 + wn + in * 8 + tg * 2;
                    atomicAdd(orow + col,     wv * c1[im][in][0]);
                    atomicAdd(orow + col + 1, wv * c1[im][in][1]);
                }
            }
            if (mr1 < ne) {
                const int p = seg0 + mr1; const float wv = g_pair_w[p];
                float* orow = O + (size_t)g_pair_tok[p] * NH;
                #pragma unroll
                for (int in = 0; in < 4; in++) {
                    const int col = n0 + wn + in * 8 + tg * 2;
                    atomicAdd(orow + col,     wv * c1[im][in][2]);
                    atomicAdd(orow + col + 1, wv * c1[im][in][3]);
                }
            }
        }
    }
}

// ---------------- launch ----------------
extern "C" void kernel_launch(void* const* d_in, const int* in_sizes, int n_in,
                              void* d_out, int out_size) {
    const float* x   = (const float*)d_in[0];
    const float* gw  = (const float*)d_in[1];
    const float* w1  = (const float*)d_in[2];
    const float* w3  = (const float*)d_in[3];
    const float* w2  = (const float*)d_in[4];
    const float* sw1 = (const float*)d_in[5];
    const float* sw3 = (const float*)d_in[6];
    const float* sw2 = (const float*)d_in[7];
    const float* sgw = (const float*)d_in[8];
    float* out = (float*)d_out;

    const int SM_SU = 3 * (128 * 80 + 2 * 16896);  // 132096  shared_up: 3 stages, 1 blk
    const int SM_MU = 2 * (64 * 80 + 2 * 16896);   // 77824   moe_up:    2 stages, 2 blk/SM
    const int SM_DN = 3 * (64 * 80 + 16896);       // 66048   down:      3 stages, 2 blk/SM
    cudaFuncSetAttribute(k_g<0,0,128,NH,NS,3,1>, cudaFuncAttributeMaxDynamicSharedMemorySize, SM_SU);
    cudaFuncSetAttribute(k_g<0,1,64,NH,NI,2,2>,  cudaFuncAttributeMaxDynamicSharedMemorySize, SM_MU);
    cudaFuncSetAttribute(k_g<1,0,64,NS,NH,3,2>,  cudaFuncAttributeMaxDynamicSharedMemorySize, SM_DN);
    cudaFuncSetAttribute(k_g<2,1,64,NI,NH,3,2>,  cudaFuncAttributeMaxDynamicSharedMemorySize, SM_DN);

    // order chosen so the profiler's sampled launch (#4) is k_moe_up
    k_pre<<<NT * NH / 4 / 256, 256>>>(x);
    k_router<<<NT / 4, 256>>>(x, gw, sgw);
    k_scansc<<<1, 512>>>();
    // routed up: g_Ab = silu(gather(xh)@w1e)*(gather(xh)@w3e)
    k_g<0,1,64,NH,NI,2,2><<<dim3(NI/128, NE, 8), 256, SM_MU>>>(w1, w3, nullptr);
    // shared up: g_Bs = silu(xh@sw1)*(xh@sw3)
    k_g<0,0,128,NH,NS,3,1><<<dim3(NS/128, NT/128), 512, SM_SU>>>(sw1, sw3, nullptr);
    // shared down: out = sg * (g_Bs @ sw2)   (writes every element)
    k_g<1,0,64,NS,NH,3,2><<<dim3(NH/128, NT/64), 256, SM_DN>>>(sw2, nullptr, out);
    // routed down: out += pair_w * (g_Ab seg @ w2e)
    k_g<2,1,64,NI,NH,3,2><<<dim3(NH/128, NE, 8), 256, SM_DN>>>(w2, nullptr, out);
}